// round 3
// baseline (speedup 1.0000x reference)
#include <cuda_runtime.h>
#include <cuda_bf16.h>
#include <math.h>
#include <stdint.h>

#define HEADS   12
#define DMODEL  768
#define HDIM    64
#define BATCH   2
#define SEQ     2048
#define ROWS    (BATCH * SEQ)          // 4096
#define BH      (BATCH * HEADS)        // 24
#define NEGBIG  (-3.402823e38f)

static const long long OUT_ELEMS = (long long)ROWS * DMODEL;
static const long long W_ELEMS   = (long long)BH * SEQ * SEQ;

// Scratch (device globals: allocation-free)
__device__ float g_qw [ROWS * DMODEL];   // [b][h][s][dh]
__device__ float g_kw [ROWS * DMODEL];   // [b][h][s][dh]
__device__ float g_vwT[ROWS * DMODEL];   // [b][h][dh][s]
__device__ float g_ctx[ROWS * DMODEL];   // [b][s][d]
__device__ float g_m  [BH * SEQ];
__device__ float g_l  [BH * SEQ];
__device__ float g_wscratch[(long long)BH * SEQ * SEQ];
__device__ float g_oscratch[ROWS * DMODEL];

struct QKVArgs {
    const float* A[3];
    const float* W[3];
    const float* b[3];
    float*       C[3];
};

__device__ __forceinline__ void mma16816(float* c,
                                         uint32_t a0, uint32_t a1, uint32_t a2, uint32_t a3,
                                         uint32_t b0, uint32_t b1)
{
    asm volatile(
        "mma.sync.aligned.m16n8k16.row.col.f32.bf16.bf16.f32 "
        "{%0,%1,%2,%3}, {%4,%5,%6,%7}, {%8,%9}, {%0,%1,%2,%3};\n"
        : "+f"(c[0]), "+f"(c[1]), "+f"(c[2]), "+f"(c[3])
        : "r"(a0), "r"(a1), "r"(a2), "r"(a3), "r"(b0), "r"(b1));
}

__device__ __forceinline__ void splitstore(__nv_bfloat16* ph, __nv_bfloat16* pl, float4 f)
{
    float xs[4] = {f.x, f.y, f.z, f.w};
#pragma unroll
    for (int p = 0; p < 2; ++p) {
        float x0 = xs[2 * p], x1 = xs[2 * p + 1];
        __nv_bfloat16 h0 = __float2bfloat16(x0);
        __nv_bfloat16 h1 = __float2bfloat16(x1);
        __nv_bfloat16 l0 = __float2bfloat16(x0 - __bfloat162float(h0));
        __nv_bfloat16 l1 = __float2bfloat16(x1 - __bfloat162float(h1));
        __nv_bfloat162 vh; vh.x = h0; vh.y = h1;
        __nv_bfloat162 vl; vl.x = l0; vl.y = l1;
        *(__nv_bfloat162*)(ph + 2 * p) = vh;
        *(__nv_bfloat162*)(pl + 2 * p) = vl;
    }
}

// ---------------------------------------------------------------------------
// Projection GEMM (unchanged from R2, modes 1 and 5 only)
// ---------------------------------------------------------------------------
template<int BN, int MF, int NF, int WM, int WN, int MODE>
__global__ void __launch_bounds__(256)
mma_gemm(const float* __restrict__ Ag, int lda,
         const float* __restrict__ Bg, int ldb,
         float* __restrict__ Cg,
         const float* __restrict__ biasg,
         int K, QKVArgs qa)
{
    constexpr int BM  = 128;
    constexpr int BKP = 18;
    constexpr int LB4 = (BN * 16) / (256 * 4);
    static_assert(WM * WN == 8, "8 warps");

    __shared__ __nv_bfloat16 Ah[2][BM][BKP], Al[2][BM][BKP];
    __shared__ __nv_bfloat16 Bh[2][BN][BKP], Bl[2][BN][BKP];

    const int tid = threadIdx.x;
    const int wid = tid >> 5, lane = tid & 31;
    const int g = lane >> 2, t = lane & 3;
    const int wm = wid % WM, wn = wid / WM;
    const int m0 = blockIdx.x * BM;
    const int n0 = blockIdx.y * BN;
    const int z  = blockIdx.z;

    const float* Ap;
    const float* Bp;
    const float* biasp = biasg;
    if (MODE == 5) { Ap = qa.A[z]; Bp = qa.W[z]; biasp = qa.b[z]; }
    else           { Ap = Ag; Bp = Bg; }

    const int ar = tid >> 1, ac = (tid & 1) * 8;
    const int br = (LB4 == 2) ? (tid >> 1) : (tid >> 2);
    const int bc = (LB4 == 2) ? ((tid & 1) * 8) : ((tid & 3) * 4);

    float acc[MF][NF][4] = {};
    float4 fa0, fa1, fb0, fb1;

    auto fetch = [&](int k0) {
        const float* arow = Ap + (size_t)(m0 + ar) * lda + k0 + ac;
        fa0 = *(const float4*)arow;
        fa1 = *(const float4*)(arow + 4);
        const float* brow = Bp + (size_t)(n0 + br) * ldb + k0 + bc;
        fb0 = *(const float4*)brow;
        if (LB4 == 2) fb1 = *(const float4*)(brow + 4);
    };
    auto sto = [&](int buf) {
        splitstore(&Ah[buf][ar][ac], &Al[buf][ar][ac], fa0);
        splitstore(&Ah[buf][ar][ac + 4], &Al[buf][ar][ac + 4], fa1);
        splitstore(&Bh[buf][br][bc], &Bl[buf][br][bc], fb0);
        if (LB4 == 2) splitstore(&Bh[buf][br][bc + 4], &Bl[buf][br][bc + 4], fb1);
    };
    auto comp = [&](int buf) {
        uint32_t ahr[MF][4], alr[MF][4], bhr[NF][2], blr[NF][2];
#pragma unroll
        for (int f = 0; f < MF; ++f) {
            int rbase = wm * (MF * 16) + f * 16 + g;
#pragma unroll
            for (int j = 0; j < 4; ++j) {
                int rr = rbase + (j & 1) * 8;
                int cc = 2 * t + (j >> 1) * 8;
                ahr[f][j] = *(const uint32_t*)&Ah[buf][rr][cc];
                alr[f][j] = *(const uint32_t*)&Al[buf][rr][cc];
            }
        }
#pragma unroll
        for (int nn = 0; nn < NF; ++nn) {
            int rb = wn * (NF * 8) + nn * 8 + g;
            bhr[nn][0] = *(const uint32_t*)&Bh[buf][rb][2 * t];
            bhr[nn][1] = *(const uint32_t*)&Bh[buf][rb][2 * t + 8];
            blr[nn][0] = *(const uint32_t*)&Bl[buf][rb][2 * t];
            blr[nn][1] = *(const uint32_t*)&Bl[buf][rb][2 * t + 8];
        }
#pragma unroll
        for (int f = 0; f < MF; ++f)
#pragma unroll
            for (int nn = 0; nn < NF; ++nn) {
                mma16816(acc[f][nn], ahr[f][0], ahr[f][1], ahr[f][2], ahr[f][3],
                         bhr[nn][0], bhr[nn][1]);
                mma16816(acc[f][nn], ahr[f][0], ahr[f][1], ahr[f][2], ahr[f][3],
                         blr[nn][0], blr[nn][1]);
                mma16816(acc[f][nn], alr[f][0], alr[f][1], alr[f][2], alr[f][3],
                         bhr[nn][0], bhr[nn][1]);
            }
    };

    fetch(0);
    sto(0);
    __syncthreads();
    const int nk = K / 16;
    int buf = 0;
    for (int ki = 0; ki < nk; ++ki) {
        bool more = (ki + 1 < nk);
        if (more) fetch((ki + 1) * 16);
        comp(buf);
        if (more) { sto(buf ^ 1); __syncthreads(); buf ^= 1; }
    }

#pragma unroll
    for (int f = 0; f < MF; ++f)
#pragma unroll
        for (int nn = 0; nn < NF; ++nn)
#pragma unroll
            for (int i2 = 0; i2 < 2; ++i2) {
                int m = m0 + wm * (MF * 16) + f * 16 + g + i2 * 8;
                int n = n0 + wn * (NF * 8) + nn * 8 + 2 * t;
                float v0 = acc[f][nn][i2 * 2 + 0] + biasp[n];
                float v1 = acc[f][nn][i2 * 2 + 1] + biasp[n + 1];
                if (MODE == 1) {
                    float2 st = {v0, v1};
                    *(float2*)&Cg[(size_t)m * DMODEL + n] = st;
                } else { // MODE 5
                    int b = m >> 11, s = m & 2047;
                    int h = n >> 6,  dh = n & 63;
                    if (z < 2) {
                        float2 st = {v0, v1};
                        *(float2*)&qa.C[z][(((size_t)(b * HEADS + h)) * SEQ + s) * HDIM + dh] = st;
                    } else {
                        qa.C[2][(((size_t)(b * HEADS + h)) * HDIM + dh + 0) * SEQ + s] = v0;
                        qa.C[2][(((size_t)(b * HEADS + h)) * HDIM + dh + 1) * SEQ + s] = v1;
                    }
                }
            }
}

// ---------------------------------------------------------------------------
// Pass 1: scores (raw, masked, scaled) + per-row online (max, sumexp) stats.
// Block = 64 q-rows x full key range (16 tiles of 128). 8 warps: 2(m) x 4(n).
// ---------------------------------------------------------------------------
__global__ void __launch_bounds__(256)
scores_stats_kernel(const float* __restrict__ qw, const float* __restrict__ kw,
                    const float* __restrict__ mask, float* __restrict__ S_,
                    float* __restrict__ mrow, float* __restrict__ lrow)
{
    extern __shared__ __nv_bfloat16 smem_p1[];
    __nv_bfloat16* Qh = smem_p1;
    __nv_bfloat16* Ql = Qh + 64 * 72;
    __nv_bfloat16* Kh = Ql + 64 * 72;
    __nv_bfloat16* Kl = Kh + 128 * 72;

    const int z = blockIdx.z;
    const int bidx = z / HEADS;
    const int m0 = blockIdx.x * 64;
    const float* Q  = qw + (size_t)z * SEQ * HDIM;
    const float* Kg = kw + (size_t)z * SEQ * HDIM;
    float* S = S_ + (size_t)z * SEQ * SEQ;

    const int tid = threadIdx.x;
    const int wid = tid >> 5, lane = tid & 31;
    const int g = lane >> 2, t = lane & 3;
    const int wm = wid & 1, wn = wid >> 1;

    // Q tile 64x64 once
    {
        int r = tid >> 2, q4 = tid & 3;
        const float* src = Q + (size_t)(m0 + r) * HDIM;
#pragma unroll
        for (int j = 0; j < 4; ++j) {
            int c = (q4 + 4 * j) * 4;
            float4 f = *(const float4*)(src + c);
            splitstore(Qh + r * 72 + c, Ql + r * 72 + c, f);
        }
    }

    float rm[4], rl[4];
#pragma unroll
    for (int i = 0; i < 4; ++i) { rm[i] = NEGBIG; rl[i] = 0.f; }

    for (int it = 0; it < 16; ++it) {
        const int n0 = it * 128;
        __syncthreads();
        {
            int r = tid >> 1, h4 = tid & 1;
            const float* src = Kg + (size_t)(n0 + r) * HDIM;
#pragma unroll
            for (int j = 0; j < 8; ++j) {
                int c = (h4 + 2 * j) * 4;
                float4 f = *(const float4*)(src + c);
                splitstore(Kh + r * 72 + c, Kl + r * 72 + c, f);
            }
        }
        __syncthreads();

        float acc[2][4][4] = {};
#pragma unroll
        for (int kc = 0; kc < 4; ++kc) {
            int kb = kc * 16;
            uint32_t ah[2][4], al[2][4], bh[4][2], bl[4][2];
#pragma unroll
            for (int f = 0; f < 2; ++f) {
                int rbase = wm * 32 + f * 16 + g;
#pragma unroll
                for (int j = 0; j < 4; ++j) {
                    int rr = rbase + (j & 1) * 8;
                    int cc = kb + 2 * t + (j >> 1) * 8;
                    ah[f][j] = *(const uint32_t*)&Qh[rr * 72 + cc];
                    al[f][j] = *(const uint32_t*)&Ql[rr * 72 + cc];
                }
            }
#pragma unroll
            for (int nn = 0; nn < 4; ++nn) {
                int rb = wn * 32 + nn * 8 + g;
                bh[nn][0] = *(const uint32_t*)&Kh[rb * 72 + kb + 2 * t];
                bh[nn][1] = *(const uint32_t*)&Kh[rb * 72 + kb + 2 * t + 8];
                bl[nn][0] = *(const uint32_t*)&Kl[rb * 72 + kb + 2 * t];
                bl[nn][1] = *(const uint32_t*)&Kl[rb * 72 + kb + 2 * t + 8];
            }
#pragma unroll
            for (int f = 0; f < 2; ++f)
#pragma unroll
                for (int nn = 0; nn < 4; ++nn) {
                    mma16816(acc[f][nn], ah[f][0], ah[f][1], ah[f][2], ah[f][3], bh[nn][0], bh[nn][1]);
                    mma16816(acc[f][nn], ah[f][0], ah[f][1], ah[f][2], ah[f][3], bl[nn][0], bl[nn][1]);
                    mma16816(acc[f][nn], al[f][0], al[f][1], al[f][2], al[f][3], bh[nn][0], bh[nn][1]);
                }
        }

        // epilogue: masks per nn (independent of f,i2)
        float mk[4][2];
#pragma unroll
        for (int nn = 0; nn < 4; ++nn) {
            int gc = n0 + wn * 32 + nn * 8 + 2 * t;
            mk[nn][0] = mask[bidx * SEQ + gc];
            mk[nn][1] = mask[bidx * SEQ + gc + 1];
        }
#pragma unroll
        for (int f = 0; f < 2; ++f)
#pragma unroll
            for (int i2 = 0; i2 < 2; ++i2) {
                int rsl = f * 2 + i2;
                int rowl = wm * 32 + f * 16 + g + i2 * 8;
                float vb[8];
                bool ok[8];
                float tmax = NEGBIG;
#pragma unroll
                for (int nn = 0; nn < 4; ++nn) {
                    int gc = n0 + wn * 32 + nn * 8 + 2 * t;
                    float v0 = acc[f][nn][i2 * 2 + 0] * 0.125f;
                    float v1 = acc[f][nn][i2 * 2 + 1] * 0.125f;
                    bool o0 = (mk[nn][0] == 0.0f);
                    bool o1 = (mk[nn][1] == 0.0f);
                    float2 st;
                    st.x = o0 ? v0 : -INFINITY;
                    st.y = o1 ? v1 : -INFINITY;
                    *(float2*)&S[(size_t)(m0 + rowl) * SEQ + gc] = st;
                    vb[nn * 2 + 0] = v0; ok[nn * 2 + 0] = o0;
                    vb[nn * 2 + 1] = v1; ok[nn * 2 + 1] = o1;
                    if (o0) tmax = fmaxf(tmax, v0);
                    if (o1) tmax = fmaxf(tmax, v1);
                }
                float nm = fmaxf(rm[rsl], tmax);
                float add = 0.f;
#pragma unroll
                for (int j = 0; j < 8; ++j)
                    if (ok[j]) add += __expf(vb[j] - nm);
                rl[rsl] = rl[rsl] * __expf(rm[rsl] - nm) + add;
                rm[rsl] = nm;
            }
    }

    // reduce over t (lanes xor 1, 2)
#pragma unroll
    for (int off = 1; off <= 2; off <<= 1)
#pragma unroll
        for (int i = 0; i < 4; ++i) {
            float om = __shfl_xor_sync(0xffffffffu, rm[i], off);
            float ol = __shfl_xor_sync(0xffffffffu, rl[i], off);
            float nm = fmaxf(rm[i], om);
            rl[i] = rl[i] * __expf(rm[i] - nm) + ol * __expf(om - nm);
            rm[i] = nm;
        }

    __syncthreads();
    float2* red = (float2*)smem_p1;   // [4 wn][64 rows]
    if (t == 0) {
#pragma unroll
        for (int f = 0; f < 2; ++f)
#pragma unroll
            for (int i2 = 0; i2 < 2; ++i2) {
                int rowl = wm * 32 + f * 16 + g + i2 * 8;
                red[wn * 64 + rowl] = make_float2(rm[f * 2 + i2], rl[f * 2 + i2]);
            }
    }
    __syncthreads();
    if (tid < 64) {
        float m = NEGBIG, l = 0.f;
#pragma unroll
        for (int w = 0; w < 4; ++w) {
            float2 p = red[w * 64 + tid];
            float nm = fmaxf(m, p.x);
            l = l * __expf(m - nm) + p.y * __expf(p.x - nm);
            m = nm;
        }
        mrow[(size_t)z * SEQ + m0 + tid] = m;
        lrow[(size_t)z * SEQ + m0 + tid] = l;
    }
}

// ---------------------------------------------------------------------------
// Pass 2: weights = exp(s-m)/l written in place + fused ctx = P @ V (bf16x3)
// Block = 64 q-rows; loops 16 key-tiles of 128. 8 warps: 4(m) x 2(n of 64 dh).
// ---------------------------------------------------------------------------
__global__ void __launch_bounds__(256)
weights_ctx_kernel(float* __restrict__ W_, const float* __restrict__ vwT,
                   const float* __restrict__ mrow, const float* __restrict__ lrow,
                   float* __restrict__ ctx)
{
    extern __shared__ __nv_bfloat16 smem_p2[];
    __nv_bfloat16* Ph = smem_p2;
    __nv_bfloat16* Pl = Ph + 64 * 136;
    __nv_bfloat16* Vh = Pl + 64 * 136;
    __nv_bfloat16* Vl = Vh + 64 * 136;

    const int z = blockIdx.z;
    const int b = z / HEADS, h = z % HEADS;
    const int m0 = blockIdx.x * 64;
    float* S = W_ + (size_t)z * SEQ * SEQ;
    const float* V = vwT + (size_t)z * SEQ * HDIM;   // [64 dh][2048 s]

    const int tid = threadIdx.x;
    const int wid = tid >> 5, lane = tid & 31;
    const int g = lane >> 2, t = lane & 3;
    const int wm = wid >> 1, wn = wid & 1;

    const int lr = tid >> 2, q4 = tid & 3;
    const float mr   = mrow[(size_t)z * SEQ + m0 + lr];
    const float invl = 1.0f / lrow[(size_t)z * SEQ + m0 + lr];

    float acc[4][4] = {};

    for (int it = 0; it < 16; ++it) {
        const int k0 = it * 128;
        __syncthreads();
        {
            float* srow = S + (size_t)(m0 + lr) * SEQ + k0;
            const float* vrow = V + (size_t)lr * SEQ + k0;
#pragma unroll
            for (int j = 0; j < 8; ++j) {
                int c = (q4 + 4 * j) * 4;
                float4 f = *(float4*)(srow + c);
                f.x = __expf(f.x - mr) * invl;
                f.y = __expf(f.y - mr) * invl;
                f.z = __expf(f.z - mr) * invl;
                f.w = __expf(f.w - mr) * invl;
                *(float4*)(srow + c) = f;
                splitstore(Ph + lr * 136 + c, Pl + lr * 136 + c, f);
                float4 vf = *(const float4*)(vrow + c);
                splitstore(Vh + lr * 136 + c, Vl + lr * 136 + c, vf);
            }
        }
        __syncthreads();

#pragma unroll
        for (int kc = 0; kc < 8; ++kc) {
            int kb = kc * 16;
            uint32_t ah[4], al[4];
#pragma unroll
            for (int j = 0; j < 4; ++j) {
                int rr = wm * 16 + g + (j & 1) * 8;
                int cc = kb + 2 * t + (j >> 1) * 8;
                ah[j] = *(const uint32_t*)&Ph[rr * 136 + cc];
                al[j] = *(const uint32_t*)&Pl[rr * 136 + cc];
            }
#pragma unroll
            for (int nn = 0; nn < 4; ++nn) {
                int rb = wn * 32 + nn * 8 + g;
                uint32_t b0 = *(const uint32_t*)&Vh[rb * 136 + kb + 2 * t];
                uint32_t b1 = *(const uint32_t*)&Vh[rb * 136 + kb + 2 * t + 8];
                uint32_t c0 = *(const uint32_t*)&Vl[rb * 136 + kb + 2 * t];
                uint32_t c1 = *(const uint32_t*)&Vl[rb * 136 + kb + 2 * t + 8];
                mma16816(acc[nn], ah[0], ah[1], ah[2], ah[3], b0, b1);
                mma16816(acc[nn], ah[0], ah[1], ah[2], ah[3], c0, c1);
                mma16816(acc[nn], al[0], al[1], al[2], al[3], b0, b1);
            }
        }
    }

#pragma unroll
    for (int nn = 0; nn < 4; ++nn)
#pragma unroll
        for (int i2 = 0; i2 < 2; ++i2) {
            int s = m0 + wm * 16 + g + i2 * 8;
            int d = h * HDIM + wn * 32 + nn * 8 + 2 * t;
            float2 st = {acc[nn][i2 * 2 + 0], acc[nn][i2 * 2 + 1]};
            *(float2*)&ctx[(size_t)(b * SEQ + s) * DMODEL + d] = st;
        }
}

// ---------------------------------------------------------------------------
extern "C" void kernel_launch(void* const* d_in, const int* in_sizes, int n_in,
                              void* d_out, int out_size)
{
    const float* q    = (const float*)d_in[0];
    const float* k    = (const float*)d_in[1];
    const float* v    = (const float*)d_in[2];
    const float* mask = (const float*)d_in[3];
    const float* Wq   = (const float*)d_in[4];
    const float* bq   = (const float*)d_in[5];
    const float* Wk   = (const float*)d_in[6];
    const float* bk   = (const float*)d_in[7];
    const float* Wv   = (const float*)d_in[8];
    const float* bv   = (const float*)d_in[9];
    const float* Wo   = (const float*)d_in[10];
    const float* bo   = (const float*)d_in[11];

    float *p_qw, *p_kw, *p_vwT, *p_ctx, *p_m, *p_l, *p_wsc, *p_osc;
    cudaGetSymbolAddress((void**)&p_qw,  g_qw);
    cudaGetSymbolAddress((void**)&p_kw,  g_kw);
    cudaGetSymbolAddress((void**)&p_vwT, g_vwT);
    cudaGetSymbolAddress((void**)&p_ctx, g_ctx);
    cudaGetSymbolAddress((void**)&p_m,   g_m);
    cudaGetSymbolAddress((void**)&p_l,   g_l);
    cudaGetSymbolAddress((void**)&p_wsc, g_wscratch);
    cudaGetSymbolAddress((void**)&p_osc, g_oscratch);

    float* outp;
    float* wp;
    long long osz = (long long)out_size;
    if (osz >= OUT_ELEMS + W_ELEMS) {
        outp = (float*)d_out;
        wp   = (float*)d_out + OUT_ELEMS;
    } else if (osz == W_ELEMS) {
        wp   = (float*)d_out;
        outp = p_osc;
    } else {
        outp = (float*)d_out;
        wp   = p_wsc;
    }

    static int smem_set = 0;
    if (!smem_set) {
        cudaFuncSetAttribute(scores_stats_kernel,
                             cudaFuncAttributeMaxDynamicSharedMemorySize, 55296);
        cudaFuncSetAttribute(weights_ctx_kernel,
                             cudaFuncAttributeMaxDynamicSharedMemorySize, 69632);
        smem_set = 1;
    }

    QKVArgs qa;
    qa.A[0] = q;  qa.A[1] = k;  qa.A[2] = v;
    qa.W[0] = Wq; qa.W[1] = Wk; qa.W[2] = Wv;
    qa.b[0] = bq; qa.b[1] = bk; qa.b[2] = bv;
    qa.C[0] = p_qw; qa.C[1] = p_kw; qa.C[2] = p_vwT;
    QKVArgs qa0 = {};

    // Fused Q/K/V projections
    mma_gemm<128, 4, 4, 2, 4, 5><<<dim3(ROWS / 128, DMODEL / 128, 3), 256>>>(
        nullptr, DMODEL, nullptr, DMODEL, nullptr, nullptr, DMODEL, qa);

    // Pass 1: raw masked scores + row stats
    scores_stats_kernel<<<dim3(SEQ / 64, 1, BH), 256, 55296>>>(
        p_qw, p_kw, mask, wp, p_m, p_l);

    // Pass 2: normalize -> weights (in place) + fused ctx
    weights_ctx_kernel<<<dim3(SEQ / 64, 1, BH), 256, 69632>>>(
        wp, p_vwT, p_m, p_l, p_ctx);

    // Output projection
    mma_gemm<128, 4, 4, 2, 4, 1><<<dim3(ROWS / 128, DMODEL / 128, 1), 256>>>(
        p_ctx, DMODEL, Wo, DMODEL, outp, bo, DMODEL, qa0);
}

// round 4
// speedup vs baseline: 1.1289x; 1.1289x over previous
#include <cuda_runtime.h>
#include <cuda_bf16.h>
#include <math.h>
#include <stdint.h>

#define HEADS   12
#define DMODEL  768
#define HDIM    64
#define BATCH   2
#define SEQ     2048
#define ROWS    (BATCH * SEQ)          // 4096
#define BH      (BATCH * HEADS)        // 24
#define NEGBIG  (-3.402823e38f)

static const long long OUT_ELEMS = (long long)ROWS * DMODEL;
static const long long W_ELEMS   = (long long)BH * SEQ * SEQ;

// Scratch (device globals: allocation-free)
__device__ float g_qw [ROWS * DMODEL];                 // [b][h][s][dh]
__device__ float g_kw [ROWS * DMODEL];                 // [b][h][s][dh]
__device__ __nv_bfloat16 g_vh[(long long)BH * HDIM * SEQ];  // V^T hi  [b][h][dh][s]
__device__ __nv_bfloat16 g_vl[(long long)BH * HDIM * SEQ];  // V^T lo
__device__ float g_ctx[ROWS * DMODEL];                 // [b][s][d]
__device__ float g_m  [BH * SEQ];
__device__ float g_l  [BH * SEQ];
__device__ float2 g_pstat[(long long)BH * 16 * SEQ];   // partial (m,l) per col-block
__device__ float g_wscratch[(long long)BH * SEQ * SEQ];
__device__ float g_oscratch[ROWS * DMODEL];

struct QKVArgs {
    const float* A[3];
    const float* W[3];
    const float* b[3];
    float*       C[2];          // qw, kw
    __nv_bfloat16* vh;
    __nv_bfloat16* vl;
};

__device__ __forceinline__ void mma16816(float* c,
                                         uint32_t a0, uint32_t a1, uint32_t a2, uint32_t a3,
                                         uint32_t b0, uint32_t b1)
{
    asm volatile(
        "mma.sync.aligned.m16n8k16.row.col.f32.bf16.bf16.f32 "
        "{%0,%1,%2,%3}, {%4,%5,%6,%7}, {%8,%9}, {%0,%1,%2,%3};\n"
        : "+f"(c[0]), "+f"(c[1]), "+f"(c[2]), "+f"(c[3])
        : "r"(a0), "r"(a1), "r"(a2), "r"(a3), "r"(b0), "r"(b1));
}

__device__ __forceinline__ void splitstore(__nv_bfloat16* ph, __nv_bfloat16* pl, float4 f)
{
    float xs[4] = {f.x, f.y, f.z, f.w};
#pragma unroll
    for (int p = 0; p < 2; ++p) {
        float x0 = xs[2 * p], x1 = xs[2 * p + 1];
        __nv_bfloat16 h0 = __float2bfloat16(x0);
        __nv_bfloat16 h1 = __float2bfloat16(x1);
        __nv_bfloat16 l0 = __float2bfloat16(x0 - __bfloat162float(h0));
        __nv_bfloat16 l1 = __float2bfloat16(x1 - __bfloat162float(h1));
        __nv_bfloat162 vh; vh.x = h0; vh.y = h1;
        __nv_bfloat162 vl; vl.x = l0; vl.y = l1;
        *(__nv_bfloat162*)(ph + 2 * p) = vh;
        *(__nv_bfloat162*)(pl + 2 * p) = vl;
    }
}

// ---------------------------------------------------------------------------
// Projection GEMM. MODE 1: row-major out (+bias). MODE 5: fused QKV; z<2
// head-scatter f32; z==2 stores V^T pre-split to bf16 hi/lo.
// ---------------------------------------------------------------------------
template<int BN, int MF, int NF, int WM, int WN, int MODE>
__global__ void __launch_bounds__(256)
mma_gemm(const float* __restrict__ Ag, int lda,
         const float* __restrict__ Bg, int ldb,
         float* __restrict__ Cg,
         const float* __restrict__ biasg,
         int K, QKVArgs qa)
{
    constexpr int BM  = 128;
    constexpr int BKP = 18;
    constexpr int LB4 = (BN * 16) / (256 * 4);
    static_assert(WM * WN == 8, "8 warps");

    __shared__ __nv_bfloat16 Ah[2][BM][BKP], Al[2][BM][BKP];
    __shared__ __nv_bfloat16 Bh[2][BN][BKP], Bl[2][BN][BKP];

    const int tid = threadIdx.x;
    const int wid = tid >> 5, lane = tid & 31;
    const int g = lane >> 2, t = lane & 3;
    const int wm = wid % WM, wn = wid / WM;
    const int m0 = blockIdx.x * BM;
    const int n0 = blockIdx.y * BN;
    const int z  = blockIdx.z;

    const float* Ap;
    const float* Bp;
    const float* biasp = biasg;
    if (MODE == 5) { Ap = qa.A[z]; Bp = qa.W[z]; biasp = qa.b[z]; }
    else           { Ap = Ag; Bp = Bg; }

    const int ar = tid >> 1, ac = (tid & 1) * 8;
    const int br = (LB4 == 2) ? (tid >> 1) : (tid >> 2);
    const int bc = (LB4 == 2) ? ((tid & 1) * 8) : ((tid & 3) * 4);

    float acc[MF][NF][4] = {};
    float4 fa0, fa1, fb0, fb1;

    auto fetch = [&](int k0) {
        const float* arow = Ap + (size_t)(m0 + ar) * lda + k0 + ac;
        fa0 = *(const float4*)arow;
        fa1 = *(const float4*)(arow + 4);
        const float* brow = Bp + (size_t)(n0 + br) * ldb + k0 + bc;
        fb0 = *(const float4*)brow;
        if (LB4 == 2) fb1 = *(const float4*)(brow + 4);
    };
    auto sto = [&](int buf) {
        splitstore(&Ah[buf][ar][ac], &Al[buf][ar][ac], fa0);
        splitstore(&Ah[buf][ar][ac + 4], &Al[buf][ar][ac + 4], fa1);
        splitstore(&Bh[buf][br][bc], &Bl[buf][br][bc], fb0);
        if (LB4 == 2) splitstore(&Bh[buf][br][bc + 4], &Bl[buf][br][bc + 4], fb1);
    };
    auto comp = [&](int buf) {
        uint32_t ahr[MF][4], alr[MF][4], bhr[NF][2], blr[NF][2];
#pragma unroll
        for (int f = 0; f < MF; ++f) {
            int rbase = wm * (MF * 16) + f * 16 + g;
#pragma unroll
            for (int j = 0; j < 4; ++j) {
                int rr = rbase + (j & 1) * 8;
                int cc = 2 * t + (j >> 1) * 8;
                ahr[f][j] = *(const uint32_t*)&Ah[buf][rr][cc];
                alr[f][j] = *(const uint32_t*)&Al[buf][rr][cc];
            }
        }
#pragma unroll
        for (int nn = 0; nn < NF; ++nn) {
            int rb = wn * (NF * 8) + nn * 8 + g;
            bhr[nn][0] = *(const uint32_t*)&Bh[buf][rb][2 * t];
            bhr[nn][1] = *(const uint32_t*)&Bh[buf][rb][2 * t + 8];
            blr[nn][0] = *(const uint32_t*)&Bl[buf][rb][2 * t];
            blr[nn][1] = *(const uint32_t*)&Bl[buf][rb][2 * t + 8];
        }
#pragma unroll
        for (int f = 0; f < MF; ++f)
#pragma unroll
            for (int nn = 0; nn < NF; ++nn) {
                mma16816(acc[f][nn], ahr[f][0], ahr[f][1], ahr[f][2], ahr[f][3],
                         bhr[nn][0], bhr[nn][1]);
                mma16816(acc[f][nn], ahr[f][0], ahr[f][1], ahr[f][2], ahr[f][3],
                         blr[nn][0], blr[nn][1]);
                mma16816(acc[f][nn], alr[f][0], alr[f][1], alr[f][2], alr[f][3],
                         bhr[nn][0], bhr[nn][1]);
            }
    };

    fetch(0);
    sto(0);
    __syncthreads();
    const int nk = K / 16;
    int buf = 0;
    for (int ki = 0; ki < nk; ++ki) {
        bool more = (ki + 1 < nk);
        if (more) fetch((ki + 1) * 16);
        comp(buf);
        if (more) { sto(buf ^ 1); __syncthreads(); buf ^= 1; }
    }

#pragma unroll
    for (int f = 0; f < MF; ++f)
#pragma unroll
        for (int nn = 0; nn < NF; ++nn)
#pragma unroll
            for (int i2 = 0; i2 < 2; ++i2) {
                int m = m0 + wm * (MF * 16) + f * 16 + g + i2 * 8;
                int n = n0 + wn * (NF * 8) + nn * 8 + 2 * t;
                float v0 = acc[f][nn][i2 * 2 + 0] + biasp[n];
                float v1 = acc[f][nn][i2 * 2 + 1] + biasp[n + 1];
                if (MODE == 1) {
                    float2 st = {v0, v1};
                    *(float2*)&Cg[(size_t)m * DMODEL + n] = st;
                } else { // MODE 5
                    int b = m >> 11, s = m & 2047;
                    int h = n >> 6,  dh = n & 63;
                    if (z < 2) {
                        float2 st = {v0, v1};
                        *(float2*)&qa.C[z][(((size_t)(b * HEADS + h)) * SEQ + s) * HDIM + dh] = st;
                    } else {
                        size_t base = (((size_t)(b * HEADS + h)) * HDIM + dh) * SEQ + s;
                        __nv_bfloat16 h0 = __float2bfloat16(v0);
                        __nv_bfloat16 h1 = __float2bfloat16(v1);
                        qa.vh[base]       = h0;
                        qa.vh[base + SEQ] = h1;
                        qa.vl[base]       = __float2bfloat16(v0 - __bfloat162float(h0));
                        qa.vl[base + SEQ] = __float2bfloat16(v1 - __bfloat162float(h1));
                    }
                }
            }
}

// ---------------------------------------------------------------------------
// Scores: 128x128 tiles, raw masked scaled scores -> S, plus per-block partial
// row (max, sumexp) -> pstat[z][colblk][row]
// ---------------------------------------------------------------------------
__global__ void __launch_bounds__(256)
scores_kernel(const float* __restrict__ qw, const float* __restrict__ kw,
              const float* __restrict__ mask, float* __restrict__ S_,
              float2* __restrict__ pstat)
{
    constexpr int BKP = 18;
    __shared__ __nv_bfloat16 Ah[2][128][BKP], Al[2][128][BKP];
    __shared__ __nv_bfloat16 Bh[2][128][BKP], Bl[2][128][BKP];
    __shared__ float2 sred[4][128];

    const int tid = threadIdx.x;
    const int wid = tid >> 5, lane = tid & 31;
    const int g = lane >> 2, t = lane & 3;
    const int wm = wid & 1, wn = wid >> 1;
    const int m0 = blockIdx.x * 128, n0 = blockIdx.y * 128;
    const int z = blockIdx.z;
    const int bidx = z / HEADS;

    const float* Ap = qw + (size_t)z * SEQ * HDIM;
    const float* Bp = kw + (size_t)z * SEQ * HDIM;
    float* S = S_ + (size_t)z * SEQ * SEQ;

    const int ar = tid >> 1, ac = (tid & 1) * 8;

    float acc[4][4][4] = {};
    float4 fa0, fa1, fb0, fb1;

    auto fetch = [&](int k0) {
        const float* arow = Ap + (size_t)(m0 + ar) * HDIM + k0 + ac;
        fa0 = *(const float4*)arow;
        fa1 = *(const float4*)(arow + 4);
        const float* brow = Bp + (size_t)(n0 + ar) * HDIM + k0 + ac;
        fb0 = *(const float4*)brow;
        fb1 = *(const float4*)(brow + 4);
    };
    auto sto = [&](int buf) {
        splitstore(&Ah[buf][ar][ac], &Al[buf][ar][ac], fa0);
        splitstore(&Ah[buf][ar][ac + 4], &Al[buf][ar][ac + 4], fa1);
        splitstore(&Bh[buf][ar][ac], &Bl[buf][ar][ac], fb0);
        splitstore(&Bh[buf][ar][ac + 4], &Bl[buf][ar][ac + 4], fb1);
    };
    auto comp = [&](int buf) {
        uint32_t ahr[4][4], alr[4][4], bhr[4][2], blr[4][2];
#pragma unroll
        for (int f = 0; f < 4; ++f) {
            int rbase = wm * 64 + f * 16 + g;
#pragma unroll
            for (int j = 0; j < 4; ++j) {
                int rr = rbase + (j & 1) * 8;
                int cc = 2 * t + (j >> 1) * 8;
                ahr[f][j] = *(const uint32_t*)&Ah[buf][rr][cc];
                alr[f][j] = *(const uint32_t*)&Al[buf][rr][cc];
            }
        }
#pragma unroll
        for (int nn = 0; nn < 4; ++nn) {
            int rb = wn * 32 + nn * 8 + g;
            bhr[nn][0] = *(const uint32_t*)&Bh[buf][rb][2 * t];
            bhr[nn][1] = *(const uint32_t*)&Bh[buf][rb][2 * t + 8];
            blr[nn][0] = *(const uint32_t*)&Bl[buf][rb][2 * t];
            blr[nn][1] = *(const uint32_t*)&Bl[buf][rb][2 * t + 8];
        }
#pragma unroll
        for (int f = 0; f < 4; ++f)
#pragma unroll
            for (int nn = 0; nn < 4; ++nn) {
                mma16816(acc[f][nn], ahr[f][0], ahr[f][1], ahr[f][2], ahr[f][3],
                         bhr[nn][0], bhr[nn][1]);
                mma16816(acc[f][nn], ahr[f][0], ahr[f][1], ahr[f][2], ahr[f][3],
                         blr[nn][0], blr[nn][1]);
                mma16816(acc[f][nn], alr[f][0], alr[f][1], alr[f][2], alr[f][3],
                         bhr[nn][0], bhr[nn][1]);
            }
    };

    fetch(0); sto(0); __syncthreads();
    int buf = 0;
    for (int ki = 0; ki < 4; ++ki) {
        bool more = (ki + 1 < 4);
        if (more) fetch((ki + 1) * 16);
        comp(buf);
        if (more) { sto(buf ^ 1); __syncthreads(); buf ^= 1; }
    }

    float mk[4][2];
#pragma unroll
    for (int nn = 0; nn < 4; ++nn) {
        int gc = n0 + wn * 32 + nn * 8 + 2 * t;
        mk[nn][0] = mask[bidx * SEQ + gc];
        mk[nn][1] = mask[bidx * SEQ + gc + 1];
    }

    float pm[8], pls[8];
#pragma unroll
    for (int f = 0; f < 4; ++f)
#pragma unroll
        for (int i2 = 0; i2 < 2; ++i2) {
            int sl = f * 2 + i2;
            int rowl = wm * 64 + f * 16 + g + i2 * 8;
            float vb[8]; bool ok[8];
            float tm = NEGBIG;
#pragma unroll
            for (int nn = 0; nn < 4; ++nn) {
                int gc = n0 + wn * 32 + nn * 8 + 2 * t;
                float v0 = acc[f][nn][i2 * 2 + 0] * 0.125f;
                float v1 = acc[f][nn][i2 * 2 + 1] * 0.125f;
                bool o0 = (mk[nn][0] == 0.0f);
                bool o1 = (mk[nn][1] == 0.0f);
                float2 st;
                st.x = o0 ? v0 : -INFINITY;
                st.y = o1 ? v1 : -INFINITY;
                *(float2*)&S[(size_t)(m0 + rowl) * SEQ + gc] = st;
                vb[nn * 2 + 0] = v0; ok[nn * 2 + 0] = o0;
                vb[nn * 2 + 1] = v1; ok[nn * 2 + 1] = o1;
                if (o0) tm = fmaxf(tm, v0);
                if (o1) tm = fmaxf(tm, v1);
            }
            float tl = 0.f;
#pragma unroll
            for (int j = 0; j < 8; ++j)
                if (ok[j]) tl += __expf(vb[j] - tm);
            pm[sl] = tm; pls[sl] = tl;
        }

    // combine over t (lanes xor 1,2)
#pragma unroll
    for (int off = 1; off <= 2; off <<= 1)
#pragma unroll
        for (int sl = 0; sl < 8; ++sl) {
            float om = __shfl_xor_sync(0xffffffffu, pm[sl], off);
            float ol = __shfl_xor_sync(0xffffffffu, pls[sl], off);
            float nm = fmaxf(pm[sl], om);
            pls[sl] = pls[sl] * __expf(pm[sl] - nm) + ol * __expf(om - nm);
            pm[sl] = nm;
        }
    if (t == 0) {
#pragma unroll
        for (int f = 0; f < 4; ++f)
#pragma unroll
            for (int i2 = 0; i2 < 2; ++i2) {
                int rowl = wm * 64 + f * 16 + g + i2 * 8;
                sred[wn][rowl] = make_float2(pm[f * 2 + i2], pls[f * 2 + i2]);
            }
    }
    __syncthreads();
    if (tid < 128) {
        float m = NEGBIG, l = 0.f;
#pragma unroll
        for (int w = 0; w < 4; ++w) {
            float2 p = sred[w][tid];
            float nm = fmaxf(m, p.x);
            l = l * __expf(m - nm) + p.y * __expf(p.x - nm);
            m = nm;
        }
        pstat[((size_t)z * 16 + blockIdx.y) * SEQ + m0 + tid] = make_float2(m, l);
    }
}

// ---------------------------------------------------------------------------
__global__ void reduce_stats(const float2* __restrict__ ps,
                             float* __restrict__ mrow, float* __restrict__ lrow)
{
    int r = blockIdx.x * 256 + threadIdx.x;      // < BH*SEQ
    int z = r >> 11, row = r & 2047;
    float m = NEGBIG, l = 0.f;
#pragma unroll
    for (int cb = 0; cb < 16; ++cb) {
        float2 p = ps[((size_t)z * 16 + cb) * SEQ + row];
        float nm = fmaxf(m, p.x);
        l = l * __expf(m - nm) + p.y * __expf(p.x - nm);
        m = nm;
    }
    mrow[r] = m;
    lrow[r] = l;
}

// ---------------------------------------------------------------------------
// Fused: normalize raw S -> weights (in place, final) + ctx = P @ V (bf16x3).
// BM=64 q-rows, BK=128 per stage, 8 warps: 4(m) x 2(n).
// ---------------------------------------------------------------------------
__global__ void __launch_bounds__(256)
ctx_kernel(float* __restrict__ W_, const __nv_bfloat16* __restrict__ vh_g,
           const __nv_bfloat16* __restrict__ vl_g,
           const float* __restrict__ mrow, const float* __restrict__ lrow,
           float* __restrict__ ctx)
{
    extern __shared__ __nv_bfloat16 sm[];
    __nv_bfloat16* Ph = sm;
    __nv_bfloat16* Pl = Ph + 64 * 136;
    __nv_bfloat16* Vh = Pl + 64 * 136;
    __nv_bfloat16* Vl = Vh + 64 * 136;

    const int z = blockIdx.z;
    const int b = z / HEADS, h = z % HEADS;
    const int m0 = blockIdx.x * 64;
    float* S = W_ + (size_t)z * SEQ * SEQ;
    const __nv_bfloat16* Vhp = vh_g + (size_t)z * HDIM * SEQ;
    const __nv_bfloat16* Vlp = vl_g + (size_t)z * HDIM * SEQ;

    const int tid = threadIdx.x;
    const int wid = tid >> 5, lane = tid & 31;
    const int g = lane >> 2, t = lane & 3;
    const int wm = wid >> 1, wn = wid & 1;
    const int lr = tid >> 2, q4 = tid & 3;

    const float mr   = mrow[(size_t)z * SEQ + m0 + lr];
    const float invl = 1.0f / lrow[(size_t)z * SEQ + m0 + lr];

    float acc[4][4] = {};

    for (int it = 0; it < 16; ++it) {
        const int k0 = it * 128;
        __syncthreads();
        {
            float* srow = S + (size_t)(m0 + lr) * SEQ + k0;
#pragma unroll
            for (int j = 0; j < 8; ++j) {
                int c = (q4 + 4 * j) * 4;
                float4 f = *(float4*)(srow + c);
                f.x = __expf(f.x - mr) * invl;
                f.y = __expf(f.y - mr) * invl;
                f.z = __expf(f.z - mr) * invl;
                f.w = __expf(f.w - mr) * invl;
                *(float4*)(srow + c) = f;
                splitstore(Ph + lr * 136 + c, Pl + lr * 136 + c, f);
            }
            const uint4* vhrow = (const uint4*)(Vhp + (size_t)lr * SEQ + k0);
            const uint4* vlrow = (const uint4*)(Vlp + (size_t)lr * SEQ + k0);
            uint4* dh_ = (uint4*)(Vh + lr * 136);
            uint4* dl_ = (uint4*)(Vl + lr * 136);
#pragma unroll
            for (int j = 0; j < 4; ++j) {
                int u = q4 * 4 + j;
                dh_[u] = vhrow[u];
                dl_[u] = vlrow[u];
            }
        }
        __syncthreads();

#pragma unroll
        for (int kc = 0; kc < 8; ++kc) {
            int kb = kc * 16;
            uint32_t ah[4], al4[4];
#pragma unroll
            for (int j = 0; j < 4; ++j) {
                int rr = wm * 16 + g + (j & 1) * 8;
                int cc = kb + 2 * t + (j >> 1) * 8;
                ah[j]  = *(const uint32_t*)&Ph[rr * 136 + cc];
                al4[j] = *(const uint32_t*)&Pl[rr * 136 + cc];
            }
#pragma unroll
            for (int nn = 0; nn < 4; ++nn) {
                int rb = wn * 32 + nn * 8 + g;
                uint32_t b0 = *(const uint32_t*)&Vh[rb * 136 + kb + 2 * t];
                uint32_t b1 = *(const uint32_t*)&Vh[rb * 136 + kb + 2 * t + 8];
                uint32_t c0 = *(const uint32_t*)&Vl[rb * 136 + kb + 2 * t];
                uint32_t c1 = *(const uint32_t*)&Vl[rb * 136 + kb + 2 * t + 8];
                mma16816(acc[nn], ah[0], ah[1], ah[2], ah[3], b0, b1);
                mma16816(acc[nn], ah[0], ah[1], ah[2], ah[3], c0, c1);
                mma16816(acc[nn], al4[0], al4[1], al4[2], al4[3], b0, b1);
            }
        }
    }

#pragma unroll
    for (int nn = 0; nn < 4; ++nn)
#pragma unroll
        for (int i2 = 0; i2 < 2; ++i2) {
            int s = m0 + wm * 16 + g + i2 * 8;
            int d = h * HDIM + wn * 32 + nn * 8 + 2 * t;
            float2 st = {acc[nn][i2 * 2 + 0], acc[nn][i2 * 2 + 1]};
            *(float2*)&ctx[(size_t)(b * SEQ + s) * DMODEL + d] = st;
        }
}

// ---------------------------------------------------------------------------
extern "C" void kernel_launch(void* const* d_in, const int* in_sizes, int n_in,
                              void* d_out, int out_size)
{
    const float* q    = (const float*)d_in[0];
    const float* k    = (const float*)d_in[1];
    const float* v    = (const float*)d_in[2];
    const float* mask = (const float*)d_in[3];
    const float* Wq   = (const float*)d_in[4];
    const float* bq   = (const float*)d_in[5];
    const float* Wk   = (const float*)d_in[6];
    const float* bk   = (const float*)d_in[7];
    const float* Wv   = (const float*)d_in[8];
    const float* bv   = (const float*)d_in[9];
    const float* Wo   = (const float*)d_in[10];
    const float* bo   = (const float*)d_in[11];

    float *p_qw, *p_kw, *p_ctx, *p_m, *p_l, *p_wsc, *p_osc;
    float2* p_ps;
    __nv_bfloat16 *p_vh, *p_vl;
    cudaGetSymbolAddress((void**)&p_qw,  g_qw);
    cudaGetSymbolAddress((void**)&p_kw,  g_kw);
    cudaGetSymbolAddress((void**)&p_vh,  g_vh);
    cudaGetSymbolAddress((void**)&p_vl,  g_vl);
    cudaGetSymbolAddress((void**)&p_ctx, g_ctx);
    cudaGetSymbolAddress((void**)&p_m,   g_m);
    cudaGetSymbolAddress((void**)&p_l,   g_l);
    cudaGetSymbolAddress((void**)&p_ps,  g_pstat);
    cudaGetSymbolAddress((void**)&p_wsc, g_wscratch);
    cudaGetSymbolAddress((void**)&p_osc, g_oscratch);

    float* outp;
    float* wp;
    long long osz = (long long)out_size;
    if (osz >= OUT_ELEMS + W_ELEMS) {
        outp = (float*)d_out;
        wp   = (float*)d_out + OUT_ELEMS;
    } else if (osz == W_ELEMS) {
        wp   = (float*)d_out;
        outp = p_osc;
    } else {
        outp = (float*)d_out;
        wp   = p_wsc;
    }

    static int smem_set = 0;
    if (!smem_set) {
        cudaFuncSetAttribute(ctx_kernel,
                             cudaFuncAttributeMaxDynamicSharedMemorySize, 69632);
        smem_set = 1;
    }

    QKVArgs qa;
    qa.A[0] = q;  qa.A[1] = k;  qa.A[2] = v;
    qa.W[0] = Wq; qa.W[1] = Wk; qa.W[2] = Wv;
    qa.b[0] = bq; qa.b[1] = bk; qa.b[2] = bv;
    qa.C[0] = p_qw; qa.C[1] = p_kw;
    qa.vh = p_vh; qa.vl = p_vl;
    QKVArgs qa0 = {};

    // Fused Q/K/V projections (V emitted pre-split bf16 hi/lo, transposed)
    mma_gemm<128, 4, 4, 2, 4, 5><<<dim3(ROWS / 128, DMODEL / 128, 3), 256>>>(
        nullptr, DMODEL, nullptr, DMODEL, nullptr, nullptr, DMODEL, qa);

    // Raw masked scores + partial row stats
    scores_kernel<<<dim3(SEQ / 128, SEQ / 128, BH), 256>>>(
        p_qw, p_kw, mask, wp, p_ps);

    // Combine partial stats -> m, l per row
    reduce_stats<<<BH * SEQ / 256, 256>>>(p_ps, p_m, p_l);

    // Normalize -> final weights (in place) + fused ctx = P @ V
    ctx_kernel<<<dim3(SEQ / 64, 1, BH), 256, 69632>>>(
        wp, p_vh, p_vl, p_m, p_l, p_ctx);

    // Output projection
    mma_gemm<128, 4, 4, 2, 4, 1><<<dim3(ROWS / 128, DMODEL / 128, 1), 256>>>(
        p_ctx, DMODEL, Wo, DMODEL, outp, bo, DMODEL, qa0);
}

// round 5
// speedup vs baseline: 1.4641x; 1.2970x over previous
#include <cuda_runtime.h>
#include <cuda_bf16.h>
#include <math.h>
#include <stdint.h>

#define HEADS   12
#define DMODEL  768
#define HDIM    64
#define BATCH   2
#define SEQ     2048
#define ROWS    4096
#define BH      24
#define NEGBIG  (-3.402823e38f)

static const long long OUT_ELEMS = (long long)ROWS * DMODEL;
static const long long W_ELEMS   = (long long)BH * SEQ * SEQ;

#define XN (ROWS * DMODEL)
#define WNN (DMODEL * DMODEL)

// Scratch (device globals: allocation-free)
__device__ __nv_bfloat16 g_xh[3][XN], g_xl[3][XN];   // inputs q,k,v split hi/lo
__device__ __nv_bfloat16 g_wh[4][WNN], g_wl[4][WNN]; // Wq,Wk,Wv,Wo split
__device__ __nv_bfloat16 g_Qh[XN], g_Ql[XN];         // [b,h,s,dh]
__device__ __nv_bfloat16 g_Kh[XN], g_Kl[XN];         // [b,h,s,dh]
__device__ __nv_bfloat16 g_Vh[XN], g_Vl[XN];         // [b,h,dh,s] (transposed)
__device__ __nv_bfloat16 g_ch[XN], g_cl[XN];         // ctx split [b,s,d]
__device__ float  g_m[BH * SEQ], g_l[BH * SEQ];
__device__ float2 g_ps[BH * 16 * SEQ];
__device__ float  g_wsc[(long long)BH * SEQ * SEQ];
__device__ float  g_osc[XN];

struct ProjArgs {
    const __nv_bfloat16 *Ah[3], *Al[3], *Bh[3], *Bl[3];
    const float* bias[3];
    __nv_bfloat16 *oh[3], *ol[3];
};

__device__ __forceinline__ uint32_t smem_u32(const void* p) {
    return (uint32_t)__cvta_generic_to_shared(p);
}
__device__ __forceinline__ void cpa16(uint32_t d, const void* s) {
    asm volatile("cp.async.cg.shared.global [%0], [%1], 16;" :: "r"(d), "l"(s));
}
#define CP_COMMIT() asm volatile("cp.async.commit_group;")
#define CP_WAIT1()  asm volatile("cp.async.wait_group 1;")

__device__ __forceinline__ void mma16816(float* c,
                                         uint32_t a0, uint32_t a1, uint32_t a2, uint32_t a3,
                                         uint32_t b0, uint32_t b1)
{
    asm volatile(
        "mma.sync.aligned.m16n8k16.row.col.f32.bf16.bf16.f32 "
        "{%0,%1,%2,%3}, {%4,%5,%6,%7}, {%8,%9}, {%0,%1,%2,%3};\n"
        : "+f"(c[0]), "+f"(c[1]), "+f"(c[2]), "+f"(c[3])
        : "r"(a0), "r"(a1), "r"(a2), "r"(a3), "r"(b0), "r"(b1));
}

__device__ __forceinline__ void splitstore(__nv_bfloat16* ph, __nv_bfloat16* pl, float4 f)
{
    float xs[4] = {f.x, f.y, f.z, f.w};
#pragma unroll
    for (int p = 0; p < 2; ++p) {
        float x0 = xs[2 * p], x1 = xs[2 * p + 1];
        __nv_bfloat16 h0 = __float2bfloat16(x0);
        __nv_bfloat16 h1 = __float2bfloat16(x1);
        __nv_bfloat16 l0 = __float2bfloat16(x0 - __bfloat162float(h0));
        __nv_bfloat16 l1 = __float2bfloat16(x1 - __bfloat162float(h1));
        __nv_bfloat162 vh; vh.x = h0; vh.y = h1;
        __nv_bfloat162 vl; vl.x = l0; vl.y = l1;
        *(__nv_bfloat162*)(ph + 2 * p) = vh;
        *(__nv_bfloat162*)(pl + 2 * p) = vl;
    }
}

// ---------------------------------------------------------------------------
__global__ void split_kernel(const float* __restrict__ src,
                             __nv_bfloat16* __restrict__ hi,
                             __nv_bfloat16* __restrict__ lo, int n4)
{
    int i = blockIdx.x * 256 + threadIdx.x;
    if (i >= n4) return;
    float4 f = ((const float4*)src)[i];
    splitstore(hi + 4 * (size_t)i, lo + 4 * (size_t)i, f);
}

// ---------------------------------------------------------------------------
// Unified bf16x3 GEMM, cp.async double-buffered. C = A[M,K] @ B[N,K]^T.
// Tile 128x128x32, 8 warps (2 m x 4 n), MF=4, NF=4.
// MODE 1: fp32 out + bias. MODE 2: scores (scale, mask, S + pstat).
// MODE 5: QKV fused (z), outputs pre-split hi/lo; z==2 transposed V.
// ---------------------------------------------------------------------------
#define SP 40   // smem row stride (bf16) for 32-wide k-tile, 80B (16B-aligned)

template<int MODE>
__global__ void __launch_bounds__(256)
gemm_bf3(const __nv_bfloat16* __restrict__ Ahg, const __nv_bfloat16* __restrict__ Alg,
         const __nv_bfloat16* __restrict__ Bhg, const __nv_bfloat16* __restrict__ Blg,
         int lda, int ldb, int K,
         float* __restrict__ Cg, const float* __restrict__ biasg,
         const float* __restrict__ maskg, float2* __restrict__ pstat,
         ProjArgs pa)
{
    extern __shared__ __align__(16) char smraw[];
    __nv_bfloat16* sAh = (__nv_bfloat16*)smraw;
    __nv_bfloat16* sAl = sAh + 2 * 128 * SP;
    __nv_bfloat16* sBh = sAl + 2 * 128 * SP;
    __nv_bfloat16* sBl = sBh + 2 * 128 * SP;

    const int tid = threadIdx.x;
    const int wid = tid >> 5, lane = tid & 31;
    const int g = lane >> 2, t = lane & 3;
    const int wm = wid & 1, wn = wid >> 1;
    const int m0 = blockIdx.x * 128, n0 = blockIdx.y * 128;
    const int z  = blockIdx.z;

    const __nv_bfloat16 *Ah, *Al, *Bh, *Bl;
    const float* biasp = biasg;
    if (MODE == 5) {
        Ah = pa.Ah[z]; Al = pa.Al[z]; Bh = pa.Bh[z]; Bl = pa.Bl[z]; biasp = pa.bias[z];
    } else if (MODE == 2) {
        size_t off = (size_t)z * SEQ * HDIM;
        Ah = Ahg + off; Al = Alg + off; Bh = Bhg + off; Bl = Blg + off;
    } else {
        Ah = Ahg; Al = Alg; Bh = Bhg; Bl = Blg;
    }

    const int lrow = tid >> 1;           // 0..127
    const int lch  = (tid & 1) * 2;      // chunk pair {0,1} or {2,3} (16B chunks)

    auto issue = [&](int kt, int stg) {
        const int k0 = kt * 32;
        const __nv_bfloat16* gah = Ah + (size_t)(m0 + lrow) * lda + k0 + lch * 8;
        const __nv_bfloat16* gal = Al + (size_t)(m0 + lrow) * lda + k0 + lch * 8;
        const __nv_bfloat16* gbh = Bh + (size_t)(n0 + lrow) * ldb + k0 + lch * 8;
        const __nv_bfloat16* gbl = Bl + (size_t)(n0 + lrow) * ldb + k0 + lch * 8;
        uint32_t o = (uint32_t)((stg * 128 + lrow) * SP + lch * 8) * 2;
        uint32_t dah = smem_u32(sAh) + o, dal = smem_u32(sAl) + o;
        uint32_t dbh = smem_u32(sBh) + o, dbl = smem_u32(sBl) + o;
        cpa16(dah, gah); cpa16(dah + 16, gah + 8);
        cpa16(dal, gal); cpa16(dal + 16, gal + 8);
        cpa16(dbh, gbh); cpa16(dbh + 16, gbh + 8);
        cpa16(dbl, gbl); cpa16(dbl + 16, gbl + 8);
    };

    float acc[4][4][4] = {};

    auto compute = [&](int stg) {
        const __nv_bfloat16* pAh = sAh + stg * 128 * SP;
        const __nv_bfloat16* pAl = sAl + stg * 128 * SP;
        const __nv_bfloat16* pBh = sBh + stg * 128 * SP;
        const __nv_bfloat16* pBl = sBl + stg * 128 * SP;
#pragma unroll
        for (int kb = 0; kb < 32; kb += 16) {
            uint32_t ah[4][4], al[4][4];
#pragma unroll
            for (int f = 0; f < 4; ++f) {
                int rbase = wm * 64 + f * 16 + g;
#pragma unroll
                for (int j = 0; j < 4; ++j) {
                    int rr = rbase + (j & 1) * 8;
                    int cc = kb + 2 * t + (j >> 1) * 8;
                    ah[f][j] = *(const uint32_t*)&pAh[rr * SP + cc];
                    al[f][j] = *(const uint32_t*)&pAl[rr * SP + cc];
                }
            }
#pragma unroll
            for (int nn = 0; nn < 4; ++nn) {
                int rb = wn * 32 + nn * 8 + g;
                uint32_t b0 = *(const uint32_t*)&pBh[rb * SP + kb + 2 * t];
                uint32_t b1 = *(const uint32_t*)&pBh[rb * SP + kb + 2 * t + 8];
                uint32_t c0 = *(const uint32_t*)&pBl[rb * SP + kb + 2 * t];
                uint32_t c1 = *(const uint32_t*)&pBl[rb * SP + kb + 2 * t + 8];
#pragma unroll
                for (int f = 0; f < 4; ++f) {
                    mma16816(acc[f][nn], ah[f][0], ah[f][1], ah[f][2], ah[f][3], b0, b1);
                    mma16816(acc[f][nn], ah[f][0], ah[f][1], ah[f][2], ah[f][3], c0, c1);
                    mma16816(acc[f][nn], al[f][0], al[f][1], al[f][2], al[f][3], b0, b1);
                }
            }
        }
    };

    const int nk = K / 32;
    issue(0, 0); CP_COMMIT();
    if (nk > 1) issue(1, 1);
    CP_COMMIT();
    for (int kt = 0; kt < nk; ++kt) {
        int cur = kt & 1;
        CP_WAIT1();
        __syncthreads();
        compute(cur);
        __syncthreads();
        if (kt + 2 < nk) issue(kt + 2, cur);
        CP_COMMIT();
    }

    // ---------------- epilogues ----------------
    if (MODE == 1) {
#pragma unroll
        for (int f = 0; f < 4; ++f)
#pragma unroll
            for (int nn = 0; nn < 4; ++nn)
#pragma unroll
                for (int i2 = 0; i2 < 2; ++i2) {
                    int m = m0 + wm * 64 + f * 16 + g + i2 * 8;
                    int n = n0 + wn * 32 + nn * 8 + 2 * t;
                    float2 st = {acc[f][nn][i2 * 2 + 0] + biasp[n],
                                 acc[f][nn][i2 * 2 + 1] + biasp[n + 1]};
                    *(float2*)&Cg[(size_t)m * DMODEL + n] = st;
                }
    } else if (MODE == 5) {
#pragma unroll
        for (int f = 0; f < 4; ++f)
#pragma unroll
            for (int nn = 0; nn < 4; ++nn)
#pragma unroll
                for (int i2 = 0; i2 < 2; ++i2) {
                    int m = m0 + wm * 64 + f * 16 + g + i2 * 8;
                    int n = n0 + wn * 32 + nn * 8 + 2 * t;
                    float v0 = acc[f][nn][i2 * 2 + 0] + biasp[n];
                    float v1 = acc[f][nn][i2 * 2 + 1] + biasp[n + 1];
                    int b = m >> 11, s = m & 2047;
                    int h = n >> 6,  dh = n & 63;
                    __nv_bfloat16 h0 = __float2bfloat16(v0);
                    __nv_bfloat16 h1 = __float2bfloat16(v1);
                    __nv_bfloat16 l0 = __float2bfloat16(v0 - __bfloat162float(h0));
                    __nv_bfloat16 l1 = __float2bfloat16(v1 - __bfloat162float(h1));
                    if (z < 2) {
                        size_t idx = (((size_t)(b * HEADS + h)) * SEQ + s) * HDIM + dh;
                        __nv_bfloat162 hh; hh.x = h0; hh.y = h1;
                        __nv_bfloat162 ll; ll.x = l0; ll.y = l1;
                        *(__nv_bfloat162*)&pa.oh[z][idx] = hh;
                        *(__nv_bfloat162*)&pa.ol[z][idx] = ll;
                    } else {
                        size_t base = (((size_t)(b * HEADS + h)) * HDIM + dh) * SEQ + s;
                        pa.oh[2][base]       = h0;
                        pa.oh[2][base + SEQ] = h1;
                        pa.ol[2][base]       = l0;
                        pa.ol[2][base + SEQ] = l1;
                    }
                }
    } else { // MODE 2: scores + stats
        const int bidx = z / HEADS;
        float* S = Cg + (size_t)z * SEQ * SEQ;
        float mk[4][2];
#pragma unroll
        for (int nn = 0; nn < 4; ++nn) {
            int gc = n0 + wn * 32 + nn * 8 + 2 * t;
            mk[nn][0] = maskg[bidx * SEQ + gc];
            mk[nn][1] = maskg[bidx * SEQ + gc + 1];
        }
        float pm[8], pls[8];
#pragma unroll
        for (int f = 0; f < 4; ++f)
#pragma unroll
            for (int i2 = 0; i2 < 2; ++i2) {
                int sl = f * 2 + i2;
                int rowl = wm * 64 + f * 16 + g + i2 * 8;
                float vb[8]; bool ok[8];
                float tm = NEGBIG;
#pragma unroll
                for (int nn = 0; nn < 4; ++nn) {
                    int gc = n0 + wn * 32 + nn * 8 + 2 * t;
                    float v0 = acc[f][nn][i2 * 2 + 0] * 0.125f;
                    float v1 = acc[f][nn][i2 * 2 + 1] * 0.125f;
                    bool o0 = (mk[nn][0] == 0.0f);
                    bool o1 = (mk[nn][1] == 0.0f);
                    float2 st;
                    st.x = o0 ? v0 : -INFINITY;
                    st.y = o1 ? v1 : -INFINITY;
                    *(float2*)&S[(size_t)(m0 + rowl) * SEQ + gc] = st;
                    vb[nn * 2 + 0] = v0; ok[nn * 2 + 0] = o0;
                    vb[nn * 2 + 1] = v1; ok[nn * 2 + 1] = o1;
                    if (o0) tm = fmaxf(tm, v0);
                    if (o1) tm = fmaxf(tm, v1);
                }
                float tl = 0.f;
#pragma unroll
                for (int j = 0; j < 8; ++j)
                    if (ok[j]) tl += __expf(vb[j] - tm);
                pm[sl] = tm; pls[sl] = tl;
            }
#pragma unroll
        for (int off = 1; off <= 2; off <<= 1)
#pragma unroll
            for (int sl = 0; sl < 8; ++sl) {
                float om = __shfl_xor_sync(0xffffffffu, pm[sl], off);
                float ol = __shfl_xor_sync(0xffffffffu, pls[sl], off);
                float nm = fmaxf(pm[sl], om);
                pls[sl] = pls[sl] * __expf(pm[sl] - nm) + ol * __expf(om - nm);
                pm[sl] = nm;
            }
        float2* sred = (float2*)smraw;   // reuse smem: [4][128]
        if (t == 0) {
#pragma unroll
            for (int f = 0; f < 4; ++f)
#pragma unroll
                for (int i2 = 0; i2 < 2; ++i2) {
                    int rowl = wm * 64 + f * 16 + g + i2 * 8;
                    sred[wn * 128 + rowl] = make_float2(pm[f * 2 + i2], pls[f * 2 + i2]);
                }
        }
        __syncthreads();
        if (tid < 128) {
            float m = NEGBIG, l = 0.f;
#pragma unroll
            for (int w = 0; w < 4; ++w) {
                float2 p = sred[w * 128 + tid];
                float nm = fmaxf(m, p.x);
                l = l * __expf(m - nm) + p.y * __expf(p.x - nm);
                m = nm;
            }
            pstat[((size_t)z * 16 + blockIdx.y) * SEQ + m0 + tid] = make_float2(m, l);
        }
    }
}

// ---------------------------------------------------------------------------
__global__ void reduce_stats(const float2* __restrict__ ps,
                             float* __restrict__ mrow, float* __restrict__ lrow)
{
    int r = blockIdx.x * 256 + threadIdx.x;
    int z = r >> 11, row = r & 2047;
    float m = NEGBIG, l = 0.f;
#pragma unroll
    for (int cb = 0; cb < 16; ++cb) {
        float2 p = ps[((size_t)z * 16 + cb) * SEQ + row];
        float nm = fmaxf(m, p.x);
        l = l * __expf(m - nm) + p.y * __expf(p.x - nm);
        m = nm;
    }
    mrow[r] = m;
    lrow[r] = l;
}

// ---------------------------------------------------------------------------
// ctx: normalize raw S -> final weights (in place) + ctx = P @ V^T (bf16x3).
// BM=64, BK=128. V double-buffered via cp.async; S prefetched in registers.
// Output ctx pre-split hi/lo.
// ---------------------------------------------------------------------------
#define CSP 136

__global__ void __launch_bounds__(256)
ctx_kernel(float* __restrict__ W_, const __nv_bfloat16* __restrict__ vh_g,
           const __nv_bfloat16* __restrict__ vl_g,
           const float* __restrict__ mrow, const float* __restrict__ lrow,
           __nv_bfloat16* __restrict__ ch, __nv_bfloat16* __restrict__ cl)
{
    extern __shared__ __align__(16) char smraw[];
    __nv_bfloat16* Ph = (__nv_bfloat16*)smraw;          // [64][CSP]
    __nv_bfloat16* Pl = Ph + 64 * CSP;
    __nv_bfloat16* Vh = Pl + 64 * CSP;                  // [2][64][CSP]
    __nv_bfloat16* Vl = Vh + 2 * 64 * CSP;

    const int z = blockIdx.z;
    const int b = z / HEADS, h = z % HEADS;
    const int m0 = blockIdx.x * 64;
    float* S = W_ + (size_t)z * SEQ * SEQ;
    const __nv_bfloat16* Vhp = vh_g + (size_t)z * HDIM * SEQ;
    const __nv_bfloat16* Vlp = vl_g + (size_t)z * HDIM * SEQ;

    const int tid = threadIdx.x;
    const int wid = tid >> 5, lane = tid & 31;
    const int g = lane >> 2, t = lane & 3;
    const int wm = wid >> 1, wn = wid & 1;
    const int lr = tid >> 2, q4 = tid & 3;

    const float mr   = mrow[(size_t)z * SEQ + m0 + lr];
    const float invl = 1.0f / lrow[(size_t)z * SEQ + m0 + lr];

    auto issueV = [&](int it, int stg) {
        const int k0 = it * 128;
        const __nv_bfloat16* gh = Vhp + (size_t)lr * SEQ + k0 + q4 * 32;
        const __nv_bfloat16* gl = Vlp + (size_t)lr * SEQ + k0 + q4 * 32;
        uint32_t o = (uint32_t)((stg * 64 + lr) * CSP + q4 * 32) * 2;
        uint32_t dh_ = smem_u32(Vh) + o, dl_ = smem_u32(Vl) + o;
#pragma unroll
        for (int j = 0; j < 4; ++j) {
            cpa16(dh_ + j * 16, gh + j * 8);
            cpa16(dl_ + j * 16, gl + j * 8);
        }
    };

    float4 sreg[8];
    auto loadS = [&](int it) {
        const float* srow = S + (size_t)(m0 + lr) * SEQ + it * 128;
#pragma unroll
        for (int j = 0; j < 8; ++j)
            sreg[j] = *(const float4*)(srow + (q4 + 4 * j) * 4);
    };
    auto procS = [&](int it) {
        float* srow = S + (size_t)(m0 + lr) * SEQ + it * 128;
#pragma unroll
        for (int j = 0; j < 8; ++j) {
            int c = (q4 + 4 * j) * 4;
            float4 f = sreg[j];
            f.x = __expf(f.x - mr) * invl;
            f.y = __expf(f.y - mr) * invl;
            f.z = __expf(f.z - mr) * invl;
            f.w = __expf(f.w - mr) * invl;
            *(float4*)(srow + c) = f;
            splitstore(Ph + lr * CSP + c, Pl + lr * CSP + c, f);
        }
    };

    float acc[4][4] = {};

    loadS(0);
    issueV(0, 0); CP_COMMIT();
    issueV(1, 1); CP_COMMIT();

    for (int it = 0; it < 16; ++it) {
        int cur = it & 1;
        procS(it);
        CP_WAIT1();
        __syncthreads();
        if (it < 15) loadS(it + 1);

        const __nv_bfloat16* pVh = Vh + cur * 64 * CSP;
        const __nv_bfloat16* pVl = Vl + cur * 64 * CSP;
#pragma unroll
        for (int kc = 0; kc < 8; ++kc) {
            int kb = kc * 16;
            uint32_t ah[4], al4[4];
#pragma unroll
            for (int j = 0; j < 4; ++j) {
                int rr = wm * 16 + g + (j & 1) * 8;
                int cc = kb + 2 * t + (j >> 1) * 8;
                ah[j]  = *(const uint32_t*)&Ph[rr * CSP + cc];
                al4[j] = *(const uint32_t*)&Pl[rr * CSP + cc];
            }
#pragma unroll
            for (int nn = 0; nn < 4; ++nn) {
                int rb = wn * 32 + nn * 8 + g;
                uint32_t b0 = *(const uint32_t*)&pVh[rb * CSP + kb + 2 * t];
                uint32_t b1 = *(const uint32_t*)&pVh[rb * CSP + kb + 2 * t + 8];
                uint32_t c0 = *(const uint32_t*)&pVl[rb * CSP + kb + 2 * t];
                uint32_t c1 = *(const uint32_t*)&pVl[rb * CSP + kb + 2 * t + 8];
                mma16816(acc[nn], ah[0], ah[1], ah[2], ah[3], b0, b1);
                mma16816(acc[nn], ah[0], ah[1], ah[2], ah[3], c0, c1);
                mma16816(acc[nn], al4[0], al4[1], al4[2], al4[3], b0, b1);
            }
        }
        __syncthreads();
        if (it + 2 < 16) issueV(it + 2, cur);
        CP_COMMIT();
    }

#pragma unroll
    for (int nn = 0; nn < 4; ++nn)
#pragma unroll
        for (int i2 = 0; i2 < 2; ++i2) {
            int s = m0 + wm * 16 + g + i2 * 8;
            int d = wn * 32 + nn * 8 + 2 * t;
            float v0 = acc[nn][i2 * 2 + 0];
            float v1 = acc[nn][i2 * 2 + 1];
            size_t idx = (size_t)(b * SEQ + s) * DMODEL + h * HDIM + d;
            __nv_bfloat16 h0 = __float2bfloat16(v0);
            __nv_bfloat16 h1 = __float2bfloat16(v1);
            __nv_bfloat162 hh; hh.x = h0; hh.y = h1;
            __nv_bfloat162 ll;
            ll.x = __float2bfloat16(v0 - __bfloat162float(h0));
            ll.y = __float2bfloat16(v1 - __bfloat162float(h1));
            *(__nv_bfloat162*)&ch[idx] = hh;
            *(__nv_bfloat162*)&cl[idx] = ll;
        }
}

// ---------------------------------------------------------------------------
extern "C" void kernel_launch(void* const* d_in, const int* in_sizes, int n_in,
                              void* d_out, int out_size)
{
    const float* xin[3] = {(const float*)d_in[0], (const float*)d_in[1], (const float*)d_in[2]};
    const float* mask = (const float*)d_in[3];
    const float* Wg[4] = {(const float*)d_in[4], (const float*)d_in[6],
                          (const float*)d_in[8], (const float*)d_in[10]};
    const float* bg[4] = {(const float*)d_in[5], (const float*)d_in[7],
                          (const float*)d_in[9], (const float*)d_in[11]};

    __nv_bfloat16 *p_xh[3], *p_xl[3], *p_wh[4], *p_wl[4];
    __nv_bfloat16 *p_Qh, *p_Ql, *p_Kh, *p_Kl, *p_Vh, *p_Vl, *p_ch, *p_cl;
    float *p_m, *p_l, *p_wsc, *p_osc;
    float2* p_ps;
    {
        __nv_bfloat16 *base_h, *base_l;
        cudaGetSymbolAddress((void**)&base_h, g_xh);
        cudaGetSymbolAddress((void**)&base_l, g_xl);
        for (int i = 0; i < 3; ++i) { p_xh[i] = base_h + (size_t)i * XN; p_xl[i] = base_l + (size_t)i * XN; }
        cudaGetSymbolAddress((void**)&base_h, g_wh);
        cudaGetSymbolAddress((void**)&base_l, g_wl);
        for (int i = 0; i < 4; ++i) { p_wh[i] = base_h + (size_t)i * WNN; p_wl[i] = base_l + (size_t)i * WNN; }
    }
    cudaGetSymbolAddress((void**)&p_Qh, g_Qh); cudaGetSymbolAddress((void**)&p_Ql, g_Ql);
    cudaGetSymbolAddress((void**)&p_Kh, g_Kh); cudaGetSymbolAddress((void**)&p_Kl, g_Kl);
    cudaGetSymbolAddress((void**)&p_Vh, g_Vh); cudaGetSymbolAddress((void**)&p_Vl, g_Vl);
    cudaGetSymbolAddress((void**)&p_ch, g_ch); cudaGetSymbolAddress((void**)&p_cl, g_cl);
    cudaGetSymbolAddress((void**)&p_m, g_m);   cudaGetSymbolAddress((void**)&p_l, g_l);
    cudaGetSymbolAddress((void**)&p_ps, g_ps);
    cudaGetSymbolAddress((void**)&p_wsc, g_wsc);
    cudaGetSymbolAddress((void**)&p_osc, g_osc);

    float* outp;
    float* wp;
    long long osz = (long long)out_size;
    if (osz >= OUT_ELEMS + W_ELEMS) {
        outp = (float*)d_out;
        wp   = (float*)d_out + OUT_ELEMS;
    } else if (osz == W_ELEMS) {
        wp   = (float*)d_out;
        outp = p_osc;
    } else {
        outp = (float*)d_out;
        wp   = p_wsc;
    }

    cudaFuncSetAttribute(gemm_bf3<5>, cudaFuncAttributeMaxDynamicSharedMemorySize, 81920);
    cudaFuncSetAttribute(gemm_bf3<2>, cudaFuncAttributeMaxDynamicSharedMemorySize, 81920);
    cudaFuncSetAttribute(gemm_bf3<1>, cudaFuncAttributeMaxDynamicSharedMemorySize, 81920);
    cudaFuncSetAttribute(ctx_kernel, cudaFuncAttributeMaxDynamicSharedMemorySize, 104448);

    // Pre-split inputs and weights to bf16 hi/lo
    for (int i = 0; i < 3; ++i)
        split_kernel<<<XN / 4 / 256, 256>>>(xin[i], p_xh[i], p_xl[i], XN / 4);
    for (int i = 0; i < 4; ++i)
        split_kernel<<<WNN / 4 / 256, 256>>>(Wg[i], p_wh[i], p_wl[i], WNN / 4);

    ProjArgs pa = {};
    for (int i = 0; i < 3; ++i) {
        pa.Ah[i] = p_xh[i]; pa.Al[i] = p_xl[i];
        pa.Bh[i] = p_wh[i]; pa.Bl[i] = p_wl[i];
        pa.bias[i] = bg[i];
    }
    pa.oh[0] = p_Qh; pa.ol[0] = p_Ql;
    pa.oh[1] = p_Kh; pa.ol[1] = p_Kl;
    pa.oh[2] = p_Vh; pa.ol[2] = p_Vl;
    ProjArgs pa0 = {};

    // Fused Q/K/V projections
    gemm_bf3<5><<<dim3(ROWS / 128, DMODEL / 128, 3), 256, 81920>>>(
        nullptr, nullptr, nullptr, nullptr, DMODEL, DMODEL, DMODEL,
        nullptr, nullptr, nullptr, nullptr, pa);

    // Scores + partial stats
    gemm_bf3<2><<<dim3(SEQ / 128, SEQ / 128, BH), 256, 81920>>>(
        p_Qh, p_Ql, p_Kh, p_Kl, HDIM, HDIM, HDIM,
        wp, nullptr, mask, p_ps, pa0);

    // Combine partial stats
    reduce_stats<<<BH * SEQ / 256, 256>>>(p_ps, p_m, p_l);

    // Normalize -> weights (in place) + fused ctx
    ctx_kernel<<<dim3(SEQ / 64, 1, BH), 256, 104448>>>(
        wp, p_Vh, p_Vl, p_m, p_l, p_ch, p_cl);

    // Output projection
    gemm_bf3<1><<<dim3(ROWS / 128, DMODEL / 128, 1), 256, 81920>>>(
        p_ch, p_cl, p_wh[3], p_wl[3], DMODEL, DMODEL, DMODEL,
        outp, bg[3], nullptr, nullptr, pa0);
}

// round 6
// speedup vs baseline: 1.4951x; 1.0212x over previous
#include <cuda_runtime.h>
#include <cuda_bf16.h>
#include <math.h>
#include <stdint.h>

#define HEADS   12
#define DMODEL  768
#define HDIM    64
#define BATCH   2
#define SEQ     2048
#define ROWS    4096
#define BH      24
#define NEGBIG  (-3.402823e38f)

static const long long OUT_ELEMS = (long long)ROWS * DMODEL;
static const long long W_ELEMS   = (long long)BH * SEQ * SEQ;

#define XN (ROWS * DMODEL)
#define WNN (DMODEL * DMODEL)

// Scratch (device globals: allocation-free)
__device__ __nv_bfloat16 g_xh[3][XN], g_xl[3][XN];   // inputs q,k,v split hi/lo
__device__ __nv_bfloat16 g_wh[4][WNN], g_wl[4][WNN]; // Wq,Wk,Wv,Wo split
__device__ __nv_bfloat16 g_Qh[XN], g_Ql[XN];         // [b,h,s,dh]
__device__ __nv_bfloat16 g_Kh[XN], g_Kl[XN];         // [b,h,s,dh]
__device__ __nv_bfloat16 g_Vh[XN], g_Vl[XN];         // [b,h,dh,s] (transposed)
__device__ __nv_bfloat16 g_ch[XN], g_cl[XN];         // ctx split [b,s,d]
__device__ float  g_cp[2][XN];                       // ctx split-k partials
__device__ float  g_m[BH * SEQ], g_l[BH * SEQ];
__device__ float2 g_ps[BH * 16 * SEQ];
__device__ float  g_wsc[(long long)BH * SEQ * SEQ];
__device__ float  g_osc[XN];

struct ProjArgs {
    const __nv_bfloat16 *Ah[3], *Al[3], *Bh[3], *Bl[3];
    const float* bias[3];
    __nv_bfloat16 *oh[3], *ol[3];
};

struct SplitSeg { const float* src; __nv_bfloat16* hi; __nv_bfloat16* lo; int n4; };
struct SplitArgs { SplitSeg seg[7]; };

__device__ __forceinline__ uint32_t smem_u32(const void* p) {
    return (uint32_t)__cvta_generic_to_shared(p);
}
__device__ __forceinline__ void cpa16(uint32_t d, const void* s) {
    asm volatile("cp.async.cg.shared.global [%0], [%1], 16;" :: "r"(d), "l"(s));
}
#define CP_COMMIT() asm volatile("cp.async.commit_group;")
#define CP_WAIT1()  asm volatile("cp.async.wait_group 1;")

__device__ __forceinline__ void mma16816(float* c,
                                         uint32_t a0, uint32_t a1, uint32_t a2, uint32_t a3,
                                         uint32_t b0, uint32_t b1)
{
    asm volatile(
        "mma.sync.aligned.m16n8k16.row.col.f32.bf16.bf16.f32 "
        "{%0,%1,%2,%3}, {%4,%5,%6,%7}, {%8,%9}, {%0,%1,%2,%3};\n"
        : "+f"(c[0]), "+f"(c[1]), "+f"(c[2]), "+f"(c[3])
        : "r"(a0), "r"(a1), "r"(a2), "r"(a3), "r"(b0), "r"(b1));
}

__device__ __forceinline__ void splitstore(__nv_bfloat16* ph, __nv_bfloat16* pl, float4 f)
{
    float xs[4] = {f.x, f.y, f.z, f.w};
#pragma unroll
    for (int p = 0; p < 2; ++p) {
        float x0 = xs[2 * p], x1 = xs[2 * p + 1];
        __nv_bfloat16 h0 = __float2bfloat16(x0);
        __nv_bfloat16 h1 = __float2bfloat16(x1);
        __nv_bfloat16 l0 = __float2bfloat16(x0 - __bfloat162float(h0));
        __nv_bfloat16 l1 = __float2bfloat16(x1 - __bfloat162float(h1));
        __nv_bfloat162 vh; vh.x = h0; vh.y = h1;
        __nv_bfloat162 vl; vl.x = l0; vl.y = l1;
        *(__nv_bfloat162*)(ph + 2 * p) = vh;
        *(__nv_bfloat162*)(pl + 2 * p) = vl;
    }
}

// ---------------------------------------------------------------------------
// One launch for all 7 fp32 -> bf16 hi/lo splits
// ---------------------------------------------------------------------------
__global__ void split_all(SplitArgs a)
{
    const SplitSeg s = a.seg[blockIdx.y];
    int i = blockIdx.x * 256 + threadIdx.x;
    if (i >= s.n4) return;
    float4 f = ((const float4*)s.src)[i];
    splitstore(s.hi + 4 * (size_t)i, s.lo + 4 * (size_t)i, f);
}

// ---------------------------------------------------------------------------
// Unified bf16x3 GEMM, cp.async double-buffered. C = A[M,K] @ B[N,K]^T.
// Tile 128x128x32, 8 warps (2 m x 4 n).
// MODE 1: fp32 out + bias. MODE 2: scores (scale, mask, S + pstat).
// MODE 5: QKV fused (z), outputs pre-split hi/lo; z==2 transposed V.
// ---------------------------------------------------------------------------
#define SP 40

template<int MODE>
__global__ void __launch_bounds__(256)
gemm_bf3(const __nv_bfloat16* __restrict__ Ahg, const __nv_bfloat16* __restrict__ Alg,
         const __nv_bfloat16* __restrict__ Bhg, const __nv_bfloat16* __restrict__ Blg,
         int lda, int ldb, int K,
         float* __restrict__ Cg, const float* __restrict__ biasg,
         const float* __restrict__ maskg, float2* __restrict__ pstat,
         ProjArgs pa)
{
    extern __shared__ __align__(16) char smraw[];
    __nv_bfloat16* sAh = (__nv_bfloat16*)smraw;
    __nv_bfloat16* sAl = sAh + 2 * 128 * SP;
    __nv_bfloat16* sBh = sAl + 2 * 128 * SP;
    __nv_bfloat16* sBl = sBh + 2 * 128 * SP;

    const int tid = threadIdx.x;
    const int wid = tid >> 5, lane = tid & 31;
    const int g = lane >> 2, t = lane & 3;
    const int wm = wid & 1, wn = wid >> 1;
    const int m0 = blockIdx.x * 128, n0 = blockIdx.y * 128;
    const int z  = blockIdx.z;

    const __nv_bfloat16 *Ah, *Al, *Bh, *Bl;
    const float* biasp = biasg;
    if (MODE == 5) {
        Ah = pa.Ah[z]; Al = pa.Al[z]; Bh = pa.Bh[z]; Bl = pa.Bl[z]; biasp = pa.bias[z];
    } else if (MODE == 2) {
        size_t off = (size_t)z * SEQ * HDIM;
        Ah = Ahg + off; Al = Alg + off; Bh = Bhg + off; Bl = Blg + off;
    } else {
        Ah = Ahg; Al = Alg; Bh = Bhg; Bl = Blg;
    }

    const int lrow = tid >> 1;
    const int lch  = (tid & 1) * 2;

    auto issue = [&](int kt, int stg) {
        const int k0 = kt * 32;
        const __nv_bfloat16* gah = Ah + (size_t)(m0 + lrow) * lda + k0 + lch * 8;
        const __nv_bfloat16* gal = Al + (size_t)(m0 + lrow) * lda + k0 + lch * 8;
        const __nv_bfloat16* gbh = Bh + (size_t)(n0 + lrow) * ldb + k0 + lch * 8;
        const __nv_bfloat16* gbl = Bl + (size_t)(n0 + lrow) * ldb + k0 + lch * 8;
        uint32_t o = (uint32_t)((stg * 128 + lrow) * SP + lch * 8) * 2;
        uint32_t dah = smem_u32(sAh) + o, dal = smem_u32(sAl) + o;
        uint32_t dbh = smem_u32(sBh) + o, dbl = smem_u32(sBl) + o;
        cpa16(dah, gah); cpa16(dah + 16, gah + 8);
        cpa16(dal, gal); cpa16(dal + 16, gal + 8);
        cpa16(dbh, gbh); cpa16(dbh + 16, gbh + 8);
        cpa16(dbl, gbl); cpa16(dbl + 16, gbl + 8);
    };

    float acc[4][4][4] = {};

    auto compute = [&](int stg) {
        const __nv_bfloat16* pAh = sAh + stg * 128 * SP;
        const __nv_bfloat16* pAl = sAl + stg * 128 * SP;
        const __nv_bfloat16* pBh = sBh + stg * 128 * SP;
        const __nv_bfloat16* pBl = sBl + stg * 128 * SP;
#pragma unroll
        for (int kb = 0; kb < 32; kb += 16) {
            uint32_t ah[4][4], al[4][4];
#pragma unroll
            for (int f = 0; f < 4; ++f) {
                int rbase = wm * 64 + f * 16 + g;
#pragma unroll
                for (int j = 0; j < 4; ++j) {
                    int rr = rbase + (j & 1) * 8;
                    int cc = kb + 2 * t + (j >> 1) * 8;
                    ah[f][j] = *(const uint32_t*)&pAh[rr * SP + cc];
                    al[f][j] = *(const uint32_t*)&pAl[rr * SP + cc];
                }
            }
#pragma unroll
            for (int nn = 0; nn < 4; ++nn) {
                int rb = wn * 32 + nn * 8 + g;
                uint32_t b0 = *(const uint32_t*)&pBh[rb * SP + kb + 2 * t];
                uint32_t b1 = *(const uint32_t*)&pBh[rb * SP + kb + 2 * t + 8];
                uint32_t c0 = *(const uint32_t*)&pBl[rb * SP + kb + 2 * t];
                uint32_t c1 = *(const uint32_t*)&pBl[rb * SP + kb + 2 * t + 8];
#pragma unroll
                for (int f = 0; f < 4; ++f) {
                    mma16816(acc[f][nn], ah[f][0], ah[f][1], ah[f][2], ah[f][3], b0, b1);
                    mma16816(acc[f][nn], ah[f][0], ah[f][1], ah[f][2], ah[f][3], c0, c1);
                    mma16816(acc[f][nn], al[f][0], al[f][1], al[f][2], al[f][3], b0, b1);
                }
            }
        }
    };

    const int nk = K / 32;
    issue(0, 0); CP_COMMIT();
    if (nk > 1) issue(1, 1);
    CP_COMMIT();
    for (int kt = 0; kt < nk; ++kt) {
        int cur = kt & 1;
        CP_WAIT1();
        __syncthreads();
        compute(cur);
        __syncthreads();
        if (kt + 2 < nk) issue(kt + 2, cur);
        CP_COMMIT();
    }

    // ---------------- epilogues ----------------
    if (MODE == 1) {
#pragma unroll
        for (int f = 0; f < 4; ++f)
#pragma unroll
            for (int nn = 0; nn < 4; ++nn)
#pragma unroll
                for (int i2 = 0; i2 < 2; ++i2) {
                    int m = m0 + wm * 64 + f * 16 + g + i2 * 8;
                    int n = n0 + wn * 32 + nn * 8 + 2 * t;
                    float2 st = {acc[f][nn][i2 * 2 + 0] + biasp[n],
                                 acc[f][nn][i2 * 2 + 1] + biasp[n + 1]};
                    *(float2*)&Cg[(size_t)m * DMODEL + n] = st;
                }
    } else if (MODE == 5) {
#pragma unroll
        for (int f = 0; f < 4; ++f)
#pragma unroll
            for (int nn = 0; nn < 4; ++nn)
#pragma unroll
                for (int i2 = 0; i2 < 2; ++i2) {
                    int m = m0 + wm * 64 + f * 16 + g + i2 * 8;
                    int n = n0 + wn * 32 + nn * 8 + 2 * t;
                    float v0 = acc[f][nn][i2 * 2 + 0] + biasp[n];
                    float v1 = acc[f][nn][i2 * 2 + 1] + biasp[n + 1];
                    int b = m >> 11, s = m & 2047;
                    int h = n >> 6,  dh = n & 63;
                    __nv_bfloat16 h0 = __float2bfloat16(v0);
                    __nv_bfloat16 h1 = __float2bfloat16(v1);
                    __nv_bfloat16 l0 = __float2bfloat16(v0 - __bfloat162float(h0));
                    __nv_bfloat16 l1 = __float2bfloat16(v1 - __bfloat162float(h1));
                    if (z < 2) {
                        size_t idx = (((size_t)(b * HEADS + h)) * SEQ + s) * HDIM + dh;
                        __nv_bfloat162 hh; hh.x = h0; hh.y = h1;
                        __nv_bfloat162 ll; ll.x = l0; ll.y = l1;
                        *(__nv_bfloat162*)&pa.oh[z][idx] = hh;
                        *(__nv_bfloat162*)&pa.ol[z][idx] = ll;
                    } else {
                        size_t base = (((size_t)(b * HEADS + h)) * HDIM + dh) * SEQ + s;
                        pa.oh[2][base]       = h0;
                        pa.oh[2][base + SEQ] = h1;
                        pa.ol[2][base]       = l0;
                        pa.ol[2][base + SEQ] = l1;
                    }
                }
    } else { // MODE 2: scores + stats
        const int bidx = z / HEADS;
        float* S = Cg + (size_t)z * SEQ * SEQ;
        float mk[4][2];
#pragma unroll
        for (int nn = 0; nn < 4; ++nn) {
            int gc = n0 + wn * 32 + nn * 8 + 2 * t;
            mk[nn][0] = maskg[bidx * SEQ + gc];
            mk[nn][1] = maskg[bidx * SEQ + gc + 1];
        }
        float pm[8], pls[8];
#pragma unroll
        for (int f = 0; f < 4; ++f)
#pragma unroll
            for (int i2 = 0; i2 < 2; ++i2) {
                int sl = f * 2 + i2;
                int rowl = wm * 64 + f * 16 + g + i2 * 8;
                float vb[8]; bool ok[8];
                float tm = NEGBIG;
#pragma unroll
                for (int nn = 0; nn < 4; ++nn) {
                    int gc = n0 + wn * 32 + nn * 8 + 2 * t;
                    float v0 = acc[f][nn][i2 * 2 + 0] * 0.125f;
                    float v1 = acc[f][nn][i2 * 2 + 1] * 0.125f;
                    bool o0 = (mk[nn][0] == 0.0f);
                    bool o1 = (mk[nn][1] == 0.0f);
                    float2 st;
                    st.x = o0 ? v0 : -INFINITY;
                    st.y = o1 ? v1 : -INFINITY;
                    *(float2*)&S[(size_t)(m0 + rowl) * SEQ + gc] = st;
                    vb[nn * 2 + 0] = v0; ok[nn * 2 + 0] = o0;
                    vb[nn * 2 + 1] = v1; ok[nn * 2 + 1] = o1;
                    if (o0) tm = fmaxf(tm, v0);
                    if (o1) tm = fmaxf(tm, v1);
                }
                float tl = 0.f;
#pragma unroll
                for (int j = 0; j < 8; ++j)
                    if (ok[j]) tl += __expf(vb[j] - tm);
                pm[sl] = tm; pls[sl] = tl;
            }
#pragma unroll
        for (int off = 1; off <= 2; off <<= 1)
#pragma unroll
            for (int sl = 0; sl < 8; ++sl) {
                float om = __shfl_xor_sync(0xffffffffu, pm[sl], off);
                float ol = __shfl_xor_sync(0xffffffffu, pls[sl], off);
                float nm = fmaxf(pm[sl], om);
                pls[sl] = pls[sl] * __expf(pm[sl] - nm) + ol * __expf(om - nm);
                pm[sl] = nm;
            }
        float2* sred = (float2*)smraw;
        __syncthreads();
        if (t == 0) {
#pragma unroll
            for (int f = 0; f < 4; ++f)
#pragma unroll
                for (int i2 = 0; i2 < 2; ++i2) {
                    int rowl = wm * 64 + f * 16 + g + i2 * 8;
                    sred[wn * 128 + rowl] = make_float2(pm[f * 2 + i2], pls[f * 2 + i2]);
                }
        }
        __syncthreads();
        if (tid < 128) {
            float m = NEGBIG, l = 0.f;
#pragma unroll
            for (int w = 0; w < 4; ++w) {
                float2 p = sred[w * 128 + tid];
                float nm = fmaxf(m, p.x);
                l = l * __expf(m - nm) + p.y * __expf(p.x - nm);
                m = nm;
            }
            pstat[((size_t)z * 16 + blockIdx.y) * SEQ + m0 + tid] = make_float2(m, l);
        }
    }
}

// ---------------------------------------------------------------------------
__global__ void reduce_stats(const float2* __restrict__ ps,
                             float* __restrict__ mrow, float* __restrict__ lrow)
{
    int r = blockIdx.x * 256 + threadIdx.x;
    int z = r >> 11, row = r & 2047;
    float m = NEGBIG, l = 0.f;
#pragma unroll
    for (int cb = 0; cb < 16; ++cb) {
        float2 p = ps[((size_t)z * 16 + cb) * SEQ + row];
        float nm = fmaxf(m, p.x);
        l = l * __expf(m - nm) + p.y * __expf(p.x - nm);
        m = nm;
    }
    mrow[r] = m;
    lrow[r] = l;
}

// ---------------------------------------------------------------------------
// ctx split-K: normalize raw S -> final weights (in place, own k-half) +
// partial ctx = P @ V^T into g_cp[kh]. BM=64, BK=128, 8 k-iters per CTA.
// ---------------------------------------------------------------------------
#define CSP 136

__global__ void __launch_bounds__(256)
ctx_kernel(float* __restrict__ W_, const __nv_bfloat16* __restrict__ vh_g,
           const __nv_bfloat16* __restrict__ vl_g,
           const float* __restrict__ mrow, const float* __restrict__ lrow,
           float* __restrict__ cpart)
{
    extern __shared__ __align__(16) char smraw[];
    __nv_bfloat16* Ph = (__nv_bfloat16*)smraw;
    __nv_bfloat16* Pl = Ph + 64 * CSP;
    __nv_bfloat16* Vh = Pl + 64 * CSP;
    __nv_bfloat16* Vl = Vh + 2 * 64 * CSP;

    const int z = blockIdx.z;
    const int kh = blockIdx.y;
    const int b = z / HEADS, h = z % HEADS;
    const int m0 = blockIdx.x * 64;
    float* S = W_ + (size_t)z * SEQ * SEQ;
    const __nv_bfloat16* Vhp = vh_g + (size_t)z * HDIM * SEQ;
    const __nv_bfloat16* Vlp = vl_g + (size_t)z * HDIM * SEQ;

    const int tid = threadIdx.x;
    const int wid = tid >> 5, lane = tid & 31;
    const int g = lane >> 2, t = lane & 3;
    const int wm = wid >> 1, wn = wid & 1;
    const int lr = tid >> 2, q4 = tid & 3;

    const float mr   = mrow[(size_t)z * SEQ + m0 + lr];
    const float invl = 1.0f / lrow[(size_t)z * SEQ + m0 + lr];

    auto issueV = [&](int it, int stg) {
        const int k0 = it * 128;
        const __nv_bfloat16* gh = Vhp + (size_t)lr * SEQ + k0 + q4 * 32;
        const __nv_bfloat16* gl = Vlp + (size_t)lr * SEQ + k0 + q4 * 32;
        uint32_t o = (uint32_t)((stg * 64 + lr) * CSP + q4 * 32) * 2;
        uint32_t dh_ = smem_u32(Vh) + o, dl_ = smem_u32(Vl) + o;
#pragma unroll
        for (int j = 0; j < 4; ++j) {
            cpa16(dh_ + j * 16, gh + j * 8);
            cpa16(dl_ + j * 16, gl + j * 8);
        }
    };

    float4 sreg[8];
    auto loadS = [&](int it) {
        const float* srow = S + (size_t)(m0 + lr) * SEQ + it * 128;
#pragma unroll
        for (int j = 0; j < 8; ++j)
            sreg[j] = *(const float4*)(srow + (q4 + 4 * j) * 4);
    };
    auto procS = [&](int it) {
        float* srow = S + (size_t)(m0 + lr) * SEQ + it * 128;
#pragma unroll
        for (int j = 0; j < 8; ++j) {
            int c = (q4 + 4 * j) * 4;
            float4 f = sreg[j];
            f.x = __expf(f.x - mr) * invl;
            f.y = __expf(f.y - mr) * invl;
            f.z = __expf(f.z - mr) * invl;
            f.w = __expf(f.w - mr) * invl;
            *(float4*)(srow + c) = f;
            splitstore(Ph + lr * CSP + c, Pl + lr * CSP + c, f);
        }
    };

    float acc[4][4] = {};
    const int it0 = kh * 8;

    loadS(it0);
    issueV(it0, 0); CP_COMMIT();
    issueV(it0 + 1, 1); CP_COMMIT();

    for (int ii = 0; ii < 8; ++ii) {
        const int it = it0 + ii;
        int cur = ii & 1;
        procS(it);
        CP_WAIT1();
        __syncthreads();
        if (ii < 7) loadS(it + 1);

        const __nv_bfloat16* pVh = Vh + cur * 64 * CSP;
        const __nv_bfloat16* pVl = Vl + cur * 64 * CSP;
#pragma unroll
        for (int kc = 0; kc < 8; ++kc) {
            int kb = kc * 16;
            uint32_t ah[4], al4[4];
#pragma unroll
            for (int j = 0; j < 4; ++j) {
                int rr = wm * 16 + g + (j & 1) * 8;
                int cc = kb + 2 * t + (j >> 1) * 8;
                ah[j]  = *(const uint32_t*)&Ph[rr * CSP + cc];
                al4[j] = *(const uint32_t*)&Pl[rr * CSP + cc];
            }
#pragma unroll
            for (int nn = 0; nn < 4; ++nn) {
                int rb = wn * 32 + nn * 8 + g;
                uint32_t b0 = *(const uint32_t*)&pVh[rb * CSP + kb + 2 * t];
                uint32_t b1 = *(const uint32_t*)&pVh[rb * CSP + kb + 2 * t + 8];
                uint32_t c0 = *(const uint32_t*)&pVl[rb * CSP + kb + 2 * t];
                uint32_t c1 = *(const uint32_t*)&pVl[rb * CSP + kb + 2 * t + 8];
                mma16816(acc[nn], ah[0], ah[1], ah[2], ah[3], b0, b1);
                mma16816(acc[nn], ah[0], ah[1], ah[2], ah[3], c0, c1);
                mma16816(acc[nn], al4[0], al4[1], al4[2], al4[3], b0, b1);
            }
        }
        __syncthreads();
        if (ii + 2 < 8) issueV(it + 2, cur);
        CP_COMMIT();
    }

#pragma unroll
    for (int nn = 0; nn < 4; ++nn)
#pragma unroll
        for (int i2 = 0; i2 < 2; ++i2) {
            int s = m0 + wm * 16 + g + i2 * 8;
            int d = wn * 32 + nn * 8 + 2 * t;
            size_t idx = (size_t)(b * SEQ + s) * DMODEL + h * HDIM + d;
            float2 st = {acc[nn][i2 * 2 + 0], acc[nn][i2 * 2 + 1]};
            *(float2*)&cpart[(size_t)kh * XN + idx] = st;
        }
}

// ---------------------------------------------------------------------------
__global__ void combine_ctx(const float* __restrict__ cp,
                            __nv_bfloat16* __restrict__ ch,
                            __nv_bfloat16* __restrict__ cl)
{
    int i = blockIdx.x * 256 + threadIdx.x;    // < XN/4
    float4 a = ((const float4*)cp)[i];
    float4 b = ((const float4*)(cp + XN))[i];
    a.x += b.x; a.y += b.y; a.z += b.z; a.w += b.w;
    splitstore(ch + 4 * (size_t)i, cl + 4 * (size_t)i, a);
}

// ---------------------------------------------------------------------------
extern "C" void kernel_launch(void* const* d_in, const int* in_sizes, int n_in,
                              void* d_out, int out_size)
{
    const float* xin[3] = {(const float*)d_in[0], (const float*)d_in[1], (const float*)d_in[2]};
    const float* mask = (const float*)d_in[3];
    const float* Wg[4] = {(const float*)d_in[4], (const float*)d_in[6],
                          (const float*)d_in[8], (const float*)d_in[10]};
    const float* bg[4] = {(const float*)d_in[5], (const float*)d_in[7],
                          (const float*)d_in[9], (const float*)d_in[11]};

    __nv_bfloat16 *p_xh[3], *p_xl[3], *p_wh[4], *p_wl[4];
    __nv_bfloat16 *p_Qh, *p_Ql, *p_Kh, *p_Kl, *p_Vh, *p_Vl, *p_ch, *p_cl;
    float *p_m, *p_l, *p_wsc, *p_osc, *p_cp;
    float2* p_ps;
    {
        __nv_bfloat16 *base_h, *base_l;
        cudaGetSymbolAddress((void**)&base_h, g_xh);
        cudaGetSymbolAddress((void**)&base_l, g_xl);
        for (int i = 0; i < 3; ++i) { p_xh[i] = base_h + (size_t)i * XN; p_xl[i] = base_l + (size_t)i * XN; }
        cudaGetSymbolAddress((void**)&base_h, g_wh);
        cudaGetSymbolAddress((void**)&base_l, g_wl);
        for (int i = 0; i < 4; ++i) { p_wh[i] = base_h + (size_t)i * WNN; p_wl[i] = base_l + (size_t)i * WNN; }
    }
    cudaGetSymbolAddress((void**)&p_Qh, g_Qh); cudaGetSymbolAddress((void**)&p_Ql, g_Ql);
    cudaGetSymbolAddress((void**)&p_Kh, g_Kh); cudaGetSymbolAddress((void**)&p_Kl, g_Kl);
    cudaGetSymbolAddress((void**)&p_Vh, g_Vh); cudaGetSymbolAddress((void**)&p_Vl, g_Vl);
    cudaGetSymbolAddress((void**)&p_ch, g_ch); cudaGetSymbolAddress((void**)&p_cl, g_cl);
    cudaGetSymbolAddress((void**)&p_cp, g_cp);
    cudaGetSymbolAddress((void**)&p_m, g_m);   cudaGetSymbolAddress((void**)&p_l, g_l);
    cudaGetSymbolAddress((void**)&p_ps, g_ps);
    cudaGetSymbolAddress((void**)&p_wsc, g_wsc);
    cudaGetSymbolAddress((void**)&p_osc, g_osc);

    float* outp;
    float* wp;
    long long osz = (long long)out_size;
    if (osz >= OUT_ELEMS + W_ELEMS) {
        outp = (float*)d_out;
        wp   = (float*)d_out + OUT_ELEMS;
    } else if (osz == W_ELEMS) {
        wp   = (float*)d_out;
        outp = p_osc;
    } else {
        outp = (float*)d_out;
        wp   = p_wsc;
    }

    cudaFuncSetAttribute(gemm_bf3<5>, cudaFuncAttributeMaxDynamicSharedMemorySize, 81920);
    cudaFuncSetAttribute(gemm_bf3<2>, cudaFuncAttributeMaxDynamicSharedMemorySize, 81920);
    cudaFuncSetAttribute(gemm_bf3<1>, cudaFuncAttributeMaxDynamicSharedMemorySize, 81920);
    cudaFuncSetAttribute(ctx_kernel, cudaFuncAttributeMaxDynamicSharedMemorySize, 104448);

    // Pre-split inputs and weights to bf16 hi/lo (single launch)
    SplitArgs sa;
    for (int i = 0; i < 3; ++i)
        sa.seg[i] = SplitSeg{xin[i], p_xh[i], p_xl[i], XN / 4};
    for (int i = 0; i < 4; ++i)
        sa.seg[3 + i] = SplitSeg{Wg[i], p_wh[i], p_wl[i], WNN / 4};
    split_all<<<dim3(XN / 4 / 256, 7), 256>>>(sa);

    ProjArgs pa = {};
    for (int i = 0; i < 3; ++i) {
        pa.Ah[i] = p_xh[i]; pa.Al[i] = p_xl[i];
        pa.Bh[i] = p_wh[i]; pa.Bl[i] = p_wl[i];
        pa.bias[i] = bg[i];
    }
    pa.oh[0] = p_Qh; pa.ol[0] = p_Ql;
    pa.oh[1] = p_Kh; pa.ol[1] = p_Kl;
    pa.oh[2] = p_Vh; pa.ol[2] = p_Vl;
    ProjArgs pa0 = {};

    // Fused Q/K/V projections
    gemm_bf3<5><<<dim3(ROWS / 128, DMODEL / 128, 3), 256, 81920>>>(
        nullptr, nullptr, nullptr, nullptr, DMODEL, DMODEL, DMODEL,
        nullptr, nullptr, nullptr, nullptr, pa);

    // Scores + partial stats
    gemm_bf3<2><<<dim3(SEQ / 128, SEQ / 128, BH), 256, 81920>>>(
        p_Qh, p_Ql, p_Kh, p_Kl, HDIM, HDIM, HDIM,
        wp, nullptr, mask, p_ps, pa0);

    // Combine partial stats
    reduce_stats<<<BH * SEQ / 256, 256>>>(p_ps, p_m, p_l);

    // Normalize -> weights (in place) + split-K partial ctx
    ctx_kernel<<<dim3(SEQ / 64, 2, BH), 256, 104448>>>(
        wp, p_Vh, p_Vl, p_m, p_l, p_cp);

    // Combine ctx halves + split hi/lo
    combine_ctx<<<XN / 4 / 256, 256>>>(p_cp, p_ch, p_cl);

    // Output projection
    gemm_bf3<1><<<dim3(ROWS / 128, DMODEL / 128, 1), 256, 81920>>>(
        p_ch, p_cl, p_wh[3], p_wl[3], DMODEL, DMODEL, DMODEL,
        outp, bg[3], nullptr, nullptr, pa0);
}